// round 6
// baseline (speedup 1.0000x reference)
#include <cuda_runtime.h>
#include <cuda_bf16.h>
#include <cstdint>

#define BB 4
#define SS 1025
#define SQ 1024
#define EE 1024
#define HH 16
#define DH 64
#define BH (BB*HH)
#define EPSF 1e-5f
#define MROWS_OUT (BB*SS)     // 4100
#define MTILES_OUT 33         // 33*128 = 4224

typedef __nv_bfloat16 bf16;

// ---------------- device scratch (allocation-free) ----------------
__device__ float QS[BH*SQ*DH];          // fp32 q  (qstats)
__device__ float KS[BH*SQ*DH];          // fp32 k  (cls path)
__device__ float VS[BH*SQ*DH];          // fp32 v  (cls path)
__device__ bf16 XH[BB*SS*EE],  XL[BB*SS*EE];
__device__ bf16 WqH[EE*EE], WqL[EE*EE], WkH[EE*EE], WkL[EE*EE];
__device__ bf16 WvH[EE*EE], WvL[EE*EE], WcH[EE*EE], WcL[EE*EE];
__device__ bf16 WoH[EE*EE], WoL[EE*EE];
__device__ bf16 QH[BH*SQ*DH], QL[BH*SQ*DH], KH[BH*SQ*DH], KL[BH*SQ*DH];
__device__ bf16 VTH[BH*DH*SQ], VTL[BH*DH*SQ];        // V^T [bh][d][j]
__device__ bf16 CPTH[BH*DH*SQ], CPTL[BH*DH*SQ];      // cls_proj^T
__device__ bf16 ATH[(size_t)BH*SQ*SQ], ATL[(size_t)BH*SQ*SQ];   // attn hi/lo
__device__ bf16 ACH[(size_t)BH*SQ*SQ], ACL[(size_t)BH*SQ*SQ];   // attn_c2o hi/lo
__device__ bf16 VALSH[(size_t)MTILES_OUT*128*EE], VALSL[(size_t)MTILES_OUT*128*EE];
__device__ float CVEC[BH*DH];
__device__ float CN2[BH];
__device__ float QN2[BH*SQ];
__device__ float CQg[BH*SQ];

// ---------------- warp-mma helpers (compute_100-safe) ----------------
__device__ __forceinline__ uint32_t s2u(const void* p) {
    uint32_t a;
    asm("{ .reg .u64 t; cvta.to.shared.u64 t, %1; cvt.u32.u64 %0, t; }" : "=r"(a) : "l"(p));
    return a;
}
#define LDSM4(R0,R1,R2,R3,addr) \
    asm volatile("ldmatrix.sync.aligned.m8n8.x4.shared.b16 {%0,%1,%2,%3}, [%4];" \
        : "=r"(R0),"=r"(R1),"=r"(R2),"=r"(R3) : "r"(addr))

__device__ __forceinline__ void mma16816(float* c, uint32_t a0, uint32_t a1,
                                         uint32_t a2, uint32_t a3,
                                         uint32_t b0, uint32_t b1) {
    asm volatile(
        "mma.sync.aligned.m16n8k16.row.col.f32.bf16.bf16.f32 "
        "{%0,%1,%2,%3}, {%4,%5,%6,%7}, {%8,%9}, {%0,%1,%2,%3};"
        : "+f"(c[0]), "+f"(c[1]), "+f"(c[2]), "+f"(c[3])
        : "r"(a0), "r"(a1), "r"(a2), "r"(a3), "r"(b0), "r"(b1));
}

// one k16 step over a warp tile of MT*16 x 32 (4 n8-tiles), split-bf16 3-pass
template<int MT>
__device__ __forceinline__ void wmma_step(float (*acc)[4][4],
    uint32_t aHb, uint32_t aLb, uint32_t bHb, uint32_t bLb,
    int mrow0, int ncol0, int k0, int lane)
{
    uint32_t aH[MT][4], aL[MT][4];
    #pragma unroll
    for (int mi = 0; mi < MT; mi++) {
        uint32_t off = ((uint32_t)(mrow0 + mi*16 + (lane & 15))*40u + (uint32_t)k0 + ((lane >> 4) << 3)) * 2u;
        LDSM4(aH[mi][0], aH[mi][1], aH[mi][2], aH[mi][3], aHb + off);
        LDSM4(aL[mi][0], aL[mi][1], aL[mi][2], aL[mi][3], aLb + off);
    }
    uint32_t bHf[4][2], bLf[4][2];
    int j = lane >> 3;
    #pragma unroll
    for (int p = 0; p < 2; p++) {
        uint32_t off = ((uint32_t)(ncol0 + p*16 + ((j >> 1) << 3) + (lane & 7))*40u + (uint32_t)k0 + ((j & 1) << 3)) * 2u;
        uint32_t r0, r1, r2, r3;
        LDSM4(r0, r1, r2, r3, bHb + off);
        bHf[p*2][0] = r0; bHf[p*2][1] = r1; bHf[p*2+1][0] = r2; bHf[p*2+1][1] = r3;
        LDSM4(r0, r1, r2, r3, bLb + off);
        bLf[p*2][0] = r0; bLf[p*2][1] = r1; bLf[p*2+1][0] = r2; bLf[p*2+1][1] = r3;
    }
    #pragma unroll
    for (int mi = 0; mi < MT; mi++)
        #pragma unroll
        for (int nj = 0; nj < 4; nj++) {
            mma16816(acc[mi][nj], aH[mi][0], aH[mi][1], aH[mi][2], aH[mi][3], bHf[nj][0], bHf[nj][1]);
            mma16816(acc[mi][nj], aH[mi][0], aH[mi][1], aH[mi][2], aH[mi][3], bLf[nj][0], bLf[nj][1]);
            mma16816(acc[mi][nj], aL[mi][0], aL[mi][1], aL[mi][2], aL[mi][3], bHf[nj][0], bHf[nj][1]);
        }
}

// load nrows x 32 bf16 chunk into smem tile (stride 40 elems) via cp.async
__device__ __forceinline__ void ld_tile32(uint32_t sdst, const bf16* g, size_t rstride, int nrows) {
    int tid = threadIdx.x;
    int tot = nrows * 4;
    for (int u = tid; u < tot; u += 256) {
        int r = u >> 2, c = u & 3;
        uint32_t dst = sdst + (uint32_t)(r*80 + c*16);
        const bf16* src = g + (size_t)r * rstride + (c << 3);
        asm volatile("cp.async.cg.shared.global [%0], [%1], 16;" :: "r"(dst), "l"(src) : "memory");
    }
}
#define CPA_COMMIT() asm volatile("cp.async.commit_group;" ::: "memory")
#define CPA_WAIT1()  asm volatile("cp.async.wait_group 1;" ::: "memory")
#define CPA_WAIT0()  asm volatile("cp.async.wait_group 0;" ::: "memory")

__device__ __forceinline__ void split2(float v, bf16& h, bf16& l) {
    h = __float2bfloat16(v);
    l = __float2bfloat16(v - __bfloat162float(h));
}
__device__ __forceinline__ uint32_t pack2(bf16 a, bf16 b) {
    return (uint32_t)__bfloat16_as_ushort(a) | ((uint32_t)__bfloat16_as_ushort(b) << 16);
}

// ============================================================
// fp32 -> bf16 hi/lo split conversion. n4 = n/4
// ============================================================
__device__ __forceinline__ void conv_body(const float* __restrict__ s,
                                          bf16* __restrict__ h,
                                          bf16* __restrict__ l, int i) {
    float4 v = ((const float4*)s)[i];
    bf16 h0, h1, h2, h3, l0, l1, l2, l3;
    split2(v.x, h0, l0); split2(v.y, h1, l1); split2(v.z, h2, l2); split2(v.w, h3, l3);
    uint2 hp, lp;
    hp.x = pack2(h0, h1); hp.y = pack2(h2, h3);
    lp.x = pack2(l0, l1); lp.y = pack2(l2, l3);
    ((uint2*)h)[i] = hp;
    ((uint2*)l)[i] = lp;
}
__global__ void conv_kernel(const float* __restrict__ s, bf16* __restrict__ h,
                            bf16* __restrict__ l, int n4) {
    int i = blockIdx.x * 256 + threadIdx.x;
    if (i >= n4) return;
    conv_body(s, h, l, i);
}
// two weight tensors in one launch (blockIdx.y selects)
__global__ void convW_kernel(const float* __restrict__ s0, bf16* __restrict__ h0,
                             bf16* __restrict__ l0,
                             const float* __restrict__ s1, bf16* __restrict__ h1,
                             bf16* __restrict__ l1, int n4) {
    int i = blockIdx.x * 256 + threadIdx.x;
    if (i >= n4) return;
    if (blockIdx.y == 0) conv_body(s0, h0, l0, i);
    else                 conv_body(s1, h1, l1, i);
}

// ============================================================
// proj: 128x128 tile of (xt @ W^T + b) via warp mma. grid(8,32,4) block 256
// smem: 2 x {AH,AL,BH,BL} of 128x40 bf16 = 81920 B
// ============================================================
__global__ void __launch_bounds__(256, 2) proj_mm(
    const float* __restrict__ b0, const float* __restrict__ b1,
    const float* __restrict__ b2, const float* __restrict__ b3)
{
    extern __shared__ uint8_t dyn[];
    uint32_t sb = s2u(dyn);
    int tid = threadIdx.x, wid = tid >> 5, lane = tid & 31;

    int w = blockIdx.z;
    const bf16* WHp = (w==0)?WqH:(w==1)?WkH:(w==2)?WvH:WcH;
    const bf16* WLp = (w==0)?WqL:(w==1)?WkL:(w==2)?WvL:WcL;
    const float* bias = (w==0)?b0:(w==1)?b1:(w==2)?b2:b3;

    int m0 = blockIdx.y * 128, n0 = blockIdx.x * 128;
    int b_ = m0 >> 10, i0 = m0 & 1023;

    const bf16* aH = XH + (size_t)(b_*SS + i0 + 1)*EE;
    const bf16* aL = XL + (size_t)(b_*SS + i0 + 1)*EE;
    const bf16* bH = WHp + (size_t)n0*EE;
    const bf16* bL = WLp + (size_t)n0*EE;

    float acc[4][4][4] = {};
    int wm = wid & 1, wn = wid >> 1;
    int mrow0 = wm*64, ncol0 = wn*32;

    ld_tile32(sb,         aH, EE, 128);
    ld_tile32(sb + 10240, aL, EE, 128);
    ld_tile32(sb + 20480, bH, EE, 128);
    ld_tile32(sb + 30720, bL, EE, 128);
    CPA_COMMIT();
    int buf = 0;
    for (int ch = 0; ch < 32; ch++) {
        if (ch + 1 < 32) {
            uint32_t nb = sb + (buf^1)*40960;
            int kt = (ch + 1) * 32;
            ld_tile32(nb,         aH + kt, EE, 128);
            ld_tile32(nb + 10240, aL + kt, EE, 128);
            ld_tile32(nb + 20480, bH + kt, EE, 128);
            ld_tile32(nb + 30720, bL + kt, EE, 128);
            CPA_COMMIT();
            CPA_WAIT1();
        } else CPA_WAIT0();
        __syncthreads();
        uint32_t base = sb + buf*40960;
        wmma_step<4>(acc, base, base+10240, base+20480, base+30720, mrow0, ncol0, 0,  lane);
        wmma_step<4>(acc, base, base+10240, base+20480, base+30720, mrow0, ncol0, 16, lane);
        __syncthreads();
        buf ^= 1;
    }

    // epilogue: bias, split, scatter to head layouts
    int rbase = mrow0 + (lane >> 2);
    int cbase = ncol0 + (lane & 3)*2;
    #pragma unroll
    for (int mi = 0; mi < 4; mi++)
        #pragma unroll
        for (int half = 0; half < 2; half++) {
            int i = i0 + rbase + mi*16 + half*8;
            #pragma unroll
            for (int nj = 0; nj < 4; nj++) {
                int col = n0 + cbase + nj*8;
                int h2 = col >> 6, d2 = col & 63;
                float v0 = acc[mi][nj][half*2]   + bias[col];
                float v1 = acc[mi][nj][half*2+1] + bias[col+1];
                bf16 h0v, l0v, h1v, l1v;
                split2(v0, h0v, l0v); split2(v1, h1v, l1v);
                size_t qi = ((size_t)(b_*HH + h2)*SQ + i)*DH + d2;
                size_t ti = ((size_t)(b_*HH + h2)*DH + d2)*SQ + i;
                if (w == 0) {
                    *(float2*)&QS[qi] = make_float2(v0, v1);
                    *(uint32_t*)&QH[qi] = pack2(h0v, h1v);
                    *(uint32_t*)&QL[qi] = pack2(l0v, l1v);
                } else if (w == 1) {
                    *(float2*)&KS[qi] = make_float2(v0, v1);
                    *(uint32_t*)&KH[qi] = pack2(h0v, h1v);
                    *(uint32_t*)&KL[qi] = pack2(l0v, l1v);
                } else if (w == 2) {
                    *(float2*)&VS[qi] = make_float2(v0, v1);
                    VTH[ti] = h0v;      VTL[ti] = l0v;
                    VTH[ti + SQ] = h1v; VTL[ti + SQ] = l1v;
                } else {
                    CPTH[ti] = h0v;      CPTL[ti] = l0v;
                    CPTH[ti + SQ] = h1v; CPTL[ti + SQ] = l1v;
                }
            }
        }
}

// ============================================================
// logits: (Q K^T)*rsqrt(64*qn2). 128x128 tile, K=64. grid(8,8,64)
// ============================================================
__global__ void __launch_bounds__(256, 2) logits_mm(float* __restrict__ attn)
{
    extern __shared__ uint8_t dyn[];
    uint32_t sb = s2u(dyn);
    int tid = threadIdx.x, wid = tid >> 5, lane = tid & 31;
    int bh = blockIdx.z;
    int m0 = blockIdx.y * 128, n0 = blockIdx.x * 128;

    size_t base = (size_t)bh*SQ*DH;
    const bf16* aH = QH + base + (size_t)m0*DH;
    const bf16* aL = QL + base + (size_t)m0*DH;
    const bf16* bH = KH + base + (size_t)n0*DH;
    const bf16* bL = KL + base + (size_t)n0*DH;

    float acc[4][4][4] = {};
    int wm = wid & 1, wn = wid >> 1;
    int mrow0 = wm*64, ncol0 = wn*32;

    ld_tile32(sb,         aH, DH, 128);
    ld_tile32(sb + 10240, aL, DH, 128);
    ld_tile32(sb + 20480, bH, DH, 128);
    ld_tile32(sb + 30720, bL, DH, 128);
    CPA_COMMIT();
    int buf = 0;
    for (int ch = 0; ch < 2; ch++) {
        if (ch == 0) {
            uint32_t nb = sb + 40960;
            ld_tile32(nb,         aH + 32, DH, 128);
            ld_tile32(nb + 10240, aL + 32, DH, 128);
            ld_tile32(nb + 20480, bH + 32, DH, 128);
            ld_tile32(nb + 30720, bL + 32, DH, 128);
            CPA_COMMIT();
            CPA_WAIT1();
        } else CPA_WAIT0();
        __syncthreads();
        uint32_t tb = sb + buf*40960;
        wmma_step<4>(acc, tb, tb+10240, tb+20480, tb+30720, mrow0, ncol0, 0,  lane);
        wmma_step<4>(acc, tb, tb+10240, tb+20480, tb+30720, mrow0, ncol0, 16, lane);
        __syncthreads();
        buf ^= 1;
    }

    int rbase = mrow0 + (lane >> 2);
    int cbase = ncol0 + (lane & 3)*2;
    #pragma unroll
    for (int mi = 0; mi < 4; mi++)
        #pragma unroll
        for (int half = 0; half < 2; half++) {
            int row = m0 + rbase + mi*16 + half*8;
            float sc = rsqrtf(64.0f * QN2[(size_t)bh*SQ + row]);
            float* orow = attn + ((size_t)bh*SQ + row)*SQ + n0;
            #pragma unroll
            for (int nj = 0; nj < 4; nj++) {
                *(float2*)&orow[cbase + nj*8] =
                    make_float2(acc[mi][nj][half*2]*sc, acc[mi][nj][half*2+1]*sc);
            }
        }
}

// ============================================================
// values: [attn|ac2o] @ [V^T;CP^T] as K=2048 GEMM. M=128,N=64. grid(8,64)
// smem/buffer: AH,AL 128x40 + BH,BL 64x40 = 30720; x2 = 61440
// ============================================================
__global__ void __launch_bounds__(256, 2) values_mm()
{
    extern __shared__ uint8_t dyn[];
    uint32_t sb = s2u(dyn);
    int tid = threadIdx.x, wid = tid >> 5, lane = tid & 31;
    int bh = blockIdx.y;
    int m0 = blockIdx.x * 128;

    size_t abase = (size_t)bh*SQ*SQ + (size_t)m0*SQ;
    size_t tbase = (size_t)bh*DH*SQ;

    float acc[2][4][4] = {};
    int wm = wid & 3, wn = wid >> 2;
    int mrow0 = wm*32, ncol0 = wn*32;

    #define VLOAD(bufb, CH) do { \
        int kt_ = (CH) * 32; \
        const bf16 *ah_, *al_, *bh_, *bl_; \
        if (kt_ < 1024) { \
            ah_ = ATH + abase + kt_; al_ = ATL + abase + kt_; \
            bh_ = VTH + tbase + kt_; bl_ = VTL + tbase + kt_; \
        } else { \
            ah_ = ACH + abase + (kt_ - 1024); al_ = ACL + abase + (kt_ - 1024); \
            bh_ = CPTH + tbase + (kt_ - 1024); bl_ = CPTL + tbase + (kt_ - 1024); \
        } \
        ld_tile32((bufb),         ah_, SQ, 128); \
        ld_tile32((bufb) + 10240, al_, SQ, 128); \
        ld_tile32((bufb) + 20480, bh_, SQ, 64); \
        ld_tile32((bufb) + 25600, bl_, SQ, 64); \
        CPA_COMMIT(); \
    } while (0)

    VLOAD(sb, 0);
    int buf = 0;
    for (int ch = 0; ch < 64; ch++) {
        if (ch + 1 < 64) { VLOAD(sb + (buf^1)*30720, ch + 1); CPA_WAIT1(); }
        else CPA_WAIT0();
        __syncthreads();
        uint32_t tb = sb + buf*30720;
        wmma_step<2>(acc, tb, tb+10240, tb+20480, tb+25600, mrow0, ncol0, 0,  lane);
        wmma_step<2>(acc, tb, tb+10240, tb+20480, tb+25600, mrow0, ncol0, 16, lane);
        __syncthreads();
        buf ^= 1;
    }
    #undef VLOAD

    int b_ = bh / HH, h_ = bh % HH;
    int rbase = mrow0 + (lane >> 2);
    int cbase = ncol0 + (lane & 3)*2;
    #pragma unroll
    for (int mi = 0; mi < 2; mi++)
        #pragma unroll
        for (int half = 0; half < 2; half++) {
            int i = m0 + rbase + mi*16 + half*8;
            size_t ob = (size_t)(b_*SS + 1 + i)*EE + h_*DH;
            #pragma unroll
            for (int nj = 0; nj < 4; nj++) {
                int col = cbase + nj*8;
                float v0 = acc[mi][nj][half*2], v1 = acc[mi][nj][half*2+1];
                bf16 h0v, l0v, h1v, l1v;
                split2(v0, h0v, l0v); split2(v1, h1v, l1v);
                *(uint32_t*)&VALSH[ob + col] = pack2(h0v, h1v);
                *(uint32_t*)&VALSL[ob + col] = pack2(l0v, l1v);
            }
        }
}

// ============================================================
// out: VALS @ Wo^T + bo. grid(8,33), M guard at 4100
// ============================================================
__global__ void __launch_bounds__(256, 2) out_mm(const float* __restrict__ bo,
                                                float* __restrict__ out)
{
    extern __shared__ uint8_t dyn[];
    uint32_t sb = s2u(dyn);
    int tid = threadIdx.x, wid = tid >> 5, lane = tid & 31;
    int m0 = blockIdx.y * 128, n0 = blockIdx.x * 128;

    const bf16* aH = VALSH + (size_t)m0*EE;
    const bf16* aL = VALSL + (size_t)m0*EE;
    const bf16* bH = WoH + (size_t)n0*EE;
    const bf16* bL = WoL + (size_t)n0*EE;

    float acc[4][4][4] = {};
    int wm = wid & 1, wn = wid >> 1;
    int mrow0 = wm*64, ncol0 = wn*32;

    ld_tile32(sb,         aH, EE, 128);
    ld_tile32(sb + 10240, aL, EE, 128);
    ld_tile32(sb + 20480, bH, EE, 128);
    ld_tile32(sb + 30720, bL, EE, 128);
    CPA_COMMIT();
    int buf = 0;
    for (int ch = 0; ch < 32; ch++) {
        if (ch + 1 < 32) {
            uint32_t nb = sb + (buf^1)*40960;
            int kt = (ch + 1) * 32;
            ld_tile32(nb,         aH + kt, EE, 128);
            ld_tile32(nb + 10240, aL + kt, EE, 128);
            ld_tile32(nb + 20480, bH + kt, EE, 128);
            ld_tile32(nb + 30720, bL + kt, EE, 128);
            CPA_COMMIT();
            CPA_WAIT1();
        } else CPA_WAIT0();
        __syncthreads();
        uint32_t base = sb + buf*40960;
        wmma_step<4>(acc, base, base+10240, base+20480, base+30720, mrow0, ncol0, 0,  lane);
        wmma_step<4>(acc, base, base+10240, base+20480, base+30720, mrow0, ncol0, 16, lane);
        __syncthreads();
        buf ^= 1;
    }

    int rbase = mrow0 + (lane >> 2);
    int cbase = ncol0 + (lane & 3)*2;
    #pragma unroll
    for (int mi = 0; mi < 4; mi++)
        #pragma unroll
        for (int half = 0; half < 2; half++) {
            int mr = m0 + rbase + mi*16 + half*8;
            if (mr >= MROWS_OUT) continue;
            #pragma unroll
            for (int nj = 0; nj < 4; nj++) {
                int col = n0 + cbase + nj*8;
                *(float2*)&out[(size_t)mr*EE + col] =
                    make_float2(acc[mi][nj][half*2] + bo[col],
                                acc[mi][nj][half*2+1] + bo[col+1]);
            }
        }
}

// ============================================================
// cls token projection + CN2. grid BH, block 64
// ============================================================
__global__ void clsproj_kernel(const float* __restrict__ x,
                               const float* __restrict__ Wq,
                               const float* __restrict__ bq) {
    int bh = blockIdx.x;
    int b_ = bh / HH, h_ = bh % HH;
    int d  = threadIdx.x;
    int j  = h_*DH + d;
    const float* xr = x  + (size_t)(b_*SS)*EE;
    const float* wr = Wq + (size_t)j*EE;
    float s = 0.f;
    for (int e = 0; e < EE; e += 4) {
        float4 xv = *(const float4*)(xr + e);
        float4 wv = *(const float4*)(wr + e);
        s += xv.x*wv.x + xv.y*wv.y + xv.z*wv.z + xv.w*wv.w;
    }
    s += bq[j];
    CVEC[bh*DH + d] = s;
    __shared__ float red[64];
    red[d] = s*s; __syncthreads();
    for (int o = 32; o > 0; o >>= 1) { if (d < o) red[d] += red[d+o]; __syncthreads(); }
    if (d == 0) CN2[bh] = fmaxf(red[0], EPSF);
}

// ============================================================
// per-row q stats: QN2 and CQ. grid BH*SQ/8, block 256
// ============================================================
__global__ void qstats_kernel() {
    int row  = blockIdx.x*8 + (threadIdx.x >> 5);
    int lane = threadIdx.x & 31;
    int bh   = row >> 10;
    const float* qr = QS   + (size_t)row*DH;
    const float* cv = CVEC + bh*DH;
    float n2 = 0.f, cq = 0.f;
    #pragma unroll
    for (int d = lane; d < DH; d += 32) {
        float qv = qr[d];
        n2 += qv*qv;
        cq += qv*cv[d];
    }
    #pragma unroll
    for (int o = 16; o > 0; o >>= 1) {
        n2 += __shfl_xor_sync(0xffffffffu, n2, o);
        cq += __shfl_xor_sync(0xffffffffu, cq, o);
    }
    if (lane == 0) { QN2[row] = fmaxf(n2, EPSF); CQg[row] = cq; }
}

// ============================================================
// dual softmax: attn (in place fp32) + hi/lo splits of attn & attn_c2o
// grid BH*SQ, block 256
// ============================================================
__global__ void softmax_kernel(float* __restrict__ attn) {
    int row = blockIdx.x;
    int bh  = row >> 10;
    float* lrow = attn + (size_t)row*SQ;
    size_t sbase = (size_t)row*SQ;
    int tid = threadIdx.x;
    __shared__ float red[256];

    float l[4], cq[4];
    #pragma unroll
    for (int p = 0; p < 4; p++) {
        int j = tid + p*256;
        l[p]  = lrow[j];
        cq[p] = CQg[(size_t)bh*SQ + j];
    }

    float m = fmaxf(fmaxf(l[0],l[1]), fmaxf(l[2],l[3]));
    red[tid] = m; __syncthreads();
    #pragma unroll
    for (int o = 128; o > 0; o >>= 1) { if (tid < o) red[tid] = fmaxf(red[tid], red[tid+o]); __syncthreads(); }
    m = red[0]; __syncthreads();
    float e1[4], s1 = 0.f;
    #pragma unroll
    for (int p = 0; p < 4; p++) { e1[p] = __expf(l[p] - m); s1 += e1[p]; }
    red[tid] = s1; __syncthreads();
    #pragma unroll
    for (int o = 128; o > 0; o >>= 1) { if (tid < o) red[tid] += red[tid+o]; __syncthreads(); }
    float inv1 = 1.0f / red[0]; __syncthreads();

    float r = rsqrtf(QN2[row] * CN2[bh]);
    float l2[4];
    #pragma unroll
    for (int p = 0; p < 4; p++) l2[p] = l[p]*cq[p]*r;
    float m2 = fmaxf(fmaxf(l2[0],l2[1]), fmaxf(l2[2],l2[3]));
    red[tid] = m2; __syncthreads();
    #pragma unroll
    for (int o = 128; o > 0; o >>= 1) { if (tid < o) red[tid] = fmaxf(red[tid], red[tid+o]); __syncthreads(); }
    m2 = red[0]; __syncthreads();
    float e2[4], s2 = 0.f;
    #pragma unroll
    for (int p = 0; p < 4; p++) { e2[p] = __expf(l2[p] - m2); s2 += e2[p]; }
    red[tid] = s2; __syncthreads();
    #pragma unroll
    for (int o = 128; o > 0; o >>= 1) { if (tid < o) red[tid] += red[tid+o]; __syncthreads(); }
    float inv2 = 1.0f / red[0];

    #pragma unroll
    for (int p = 0; p < 4; p++) {
        int j = tid + p*256;
        float a1 = e1[p]*inv1;
        float a2 = e2[p]*inv2;
        lrow[j] = a1;
        bf16 h1, o1, h2, o2;
        split2(a1, h1, o1);
        split2(a2, h2, o2);
        ATH[sbase + j] = h1; ATL[sbase + j] = o1;
        ACH[sbase + j] = h2; ACL[sbase + j] = o2;
    }
}

// ============================================================
// cls path: ck softmax -> cls_out row (hi/lo into VALS). grid BH, block 256
// ============================================================
__global__ void cls_kernel() {
    int bh = blockIdx.x;
    int tid = threadIdx.x;
    const float* Kp = KS + (size_t)bh*SQ*DH;
    const float* Vp = VS + (size_t)bh*SQ*DH;
    __shared__ float p_s[SQ];
    __shared__ float red[256];
    __shared__ float c_s[DH];
    if (tid < DH) c_s[tid] = CVEC[bh*DH + tid];
    __syncthreads();

    float scale = rsqrtf(64.0f * CN2[bh]);
    float lo[4];
    #pragma unroll
    for (int p = 0; p < 4; p++) {
        int j = tid + p*256;
        const float* kr = Kp + (size_t)j*DH;
        float s = 0.f;
        #pragma unroll
        for (int d = 0; d < DH; d += 4) {
            float4 kv = *(const float4*)(kr + d);
            s += c_s[d]*kv.x + c_s[d+1]*kv.y + c_s[d+2]*kv.z + c_s[d+3]*kv.w;
        }
        lo[p] = s * scale;
    }
    float m = fmaxf(fmaxf(lo[0],lo[1]), fmaxf(lo[2],lo[3]));
    red[tid] = m; __syncthreads();
    #pragma unroll
    for (int o = 128; o > 0; o >>= 1) { if (tid < o) red[tid] = fmaxf(red[tid], red[tid+o]); __syncthreads(); }
    m = red[0]; __syncthreads();
    float e[4], s = 0.f;
    #pragma unroll
    for (int p = 0; p < 4; p++) { e[p] = __expf(lo[p] - m); s += e[p]; }
    red[tid] = s; __syncthreads();
    #pragma unroll
    for (int o = 128; o > 0; o >>= 1) { if (tid < o) red[tid] += red[tid+o]; __syncthreads(); }
    float inv = 1.0f / red[0]; __syncthreads();
    #pragma unroll
    for (int p = 0; p < 4; p++) p_s[tid + p*256] = e[p]*inv;
    __syncthreads();

    int d = tid & 63, g = tid >> 6;
    float acc = 0.f;
    for (int j = g*256; j < (g+1)*256; j++) acc += p_s[j] * Vp[(size_t)j*DH + d];
    red[tid] = acc; __syncthreads();
    if (g == 0) {
        float rsum = red[tid] + red[tid+64] + red[tid+128] + red[tid+192];
        int b_ = bh / HH, h_ = bh % HH;
        bf16 hi, lov; split2(rsum, hi, lov);
        size_t idx = (size_t)(b_*SS)*EE + h_*DH + d;
        VALSH[idx] = hi;
        VALSL[idx] = lov;
    }
}

extern "C" void kernel_launch(void* const* d_in, const int* in_sizes, int n_in,
                              void* d_out, int out_size) {
    const float* x  = (const float*)d_in[0];
    const float* Wq = (const float*)d_in[1];
    const float* bq = (const float*)d_in[2];
    const float* Wk = (const float*)d_in[3];
    const float* bk = (const float*)d_in[4];
    const float* Wv = (const float*)d_in[5];
    const float* bv = (const float*)d_in[6];
    const float* Wo = (const float*)d_in[7];
    const float* bo = (const float*)d_in[8];
    const float* Wc = (const float*)d_in[9];
    const float* bc = (const float*)d_in[10];

    float* out  = (float*)d_out;
    float* attn = out + (size_t)BB*SS*EE;

    cudaFuncSetAttribute(proj_mm,   cudaFuncAttributeMaxDynamicSharedMemorySize, 81920);
    cudaFuncSetAttribute(logits_mm, cudaFuncAttributeMaxDynamicSharedMemorySize, 81920);
    cudaFuncSetAttribute(out_mm,    cudaFuncAttributeMaxDynamicSharedMemorySize, 81920);
    cudaFuncSetAttribute(values_mm, cudaFuncAttributeMaxDynamicSharedMemorySize, 61440);

    bf16 *xh, *xl, *wqh, *wql, *wkh, *wkl, *wvh, *wvl, *wch, *wcl, *woh, *wol;
    cudaGetSymbolAddress((void**)&xh, XH);   cudaGetSymbolAddress((void**)&xl, XL);
    cudaGetSymbolAddress((void**)&wqh, WqH); cudaGetSymbolAddress((void**)&wql, WqL);
    cudaGetSymbolAddress((void**)&wkh, WkH); cudaGetSymbolAddress((void**)&wkl, WkL);
    cudaGetSymbolAddress((void**)&wvh, WvH); cudaGetSymbolAddress((void**)&wvl, WvL);
    cudaGetSymbolAddress((void**)&wch, WcH); cudaGetSymbolAddress((void**)&wcl, WcL);
    cudaGetSymbolAddress((void**)&woh, WoH); cudaGetSymbolAddress((void**)&wol, WoL);

    int nx4 = BB*SS*EE/4, nw4 = EE*EE/4;
    // launch 1: x conversion
    conv_kernel<<<(nx4+255)/256, 256>>>(x,  xh,  xl,  nx4);
    // launch 2: Wq + Wk
    convW_kernel<<<dim3((nw4+255)/256, 2), 256>>>(Wq, wqh, wql, Wk, wkh, wkl, nw4);
    // launch 3: Wv + Wc
    convW_kernel<<<dim3((nw4+255)/256, 2), 256>>>(Wv, wvh, wvl, Wc, wch, wcl, nw4);
    // launch 4: Wo
    conv_kernel<<<(nw4+255)/256, 256>>>(Wo, woh, wol, nw4);
    // launch 5: cls token projection
    clsproj_kernel<<<BH, 64>>>(x, Wq, bq);
    // launch 6: proj (target of ncu -s 5 -c 1 capture)
    proj_mm<<<dim3(8,32,4), 256, 81920>>>(bq, bk, bv, bc);
    qstats_kernel<<<BH*SQ/8, 256>>>();
    logits_mm<<<dim3(8,8,BH), 256, 81920>>>(attn);
    softmax_kernel<<<BH*SQ, 256>>>(attn);
    values_mm<<<dim3(8,BH), 256, 61440>>>();
    cls_kernel<<<BH, 256>>>();
    out_mm<<<dim3(8,33), 256, 81920>>>(bo, out);
}

// round 7
// speedup vs baseline: 1.2036x; 1.2036x over previous
#include <cuda_runtime.h>
#include <cuda_bf16.h>
#include <cstdint>

#define BB 4
#define SS 1025
#define SQ 1024
#define EE 1024
#define HH 16
#define DH 64
#define BH (BB*HH)
#define EPSF 1e-5f
#define MROWS_OUT (BB*SS)     // 4100
#define MTILES_OUT 33         // 33*128 = 4224

typedef __nv_bfloat16 bf16;

// ---------------- device scratch (allocation-free) ----------------
__device__ float QS[BH*SQ*DH];          // fp32 q  (qstats)
__device__ float KS[BH*SQ*DH];          // fp32 k  (cls path)
__device__ float VS[BH*SQ*DH];          // fp32 v  (cls path)
__device__ bf16 XH[BB*SS*EE],  XL[BB*SS*EE];
__device__ bf16 WqH[EE*EE], WqL[EE*EE], WkH[EE*EE], WkL[EE*EE];
__device__ bf16 WvH[EE*EE], WvL[EE*EE], WcH[EE*EE], WcL[EE*EE];
__device__ bf16 WoH[EE*EE], WoL[EE*EE];
__device__ bf16 QH[BH*SQ*DH], QL[BH*SQ*DH], KH[BH*SQ*DH], KL[BH*SQ*DH];
__device__ bf16 VTH[BH*DH*SQ], VTL[BH*DH*SQ];        // V^T [bh][d][j]
__device__ bf16 CPTH[BH*DH*SQ], CPTL[BH*DH*SQ];      // cls_proj^T
__device__ bf16 VALSH[(size_t)MTILES_OUT*128*EE], VALSL[(size_t)MTILES_OUT*128*EE];
__device__ float CVEC[BH*DH];
__device__ float CN2[BH];
__device__ float QN2[BH*SQ];
__device__ float CQg[BH*SQ];
__device__ float M1g[BH*SQ];            // final row max (path 1)
__device__ float S1g[BH*SQ];            // 1/rowsum (path 1)

// ---------------- warp-mma helpers ----------------
__device__ __forceinline__ uint32_t s2u(const void* p) {
    uint32_t a;
    asm("{ .reg .u64 t; cvta.to.shared.u64 t, %1; cvt.u32.u64 %0, t; }" : "=r"(a) : "l"(p));
    return a;
}
#define LDSM4(R0,R1,R2,R3,addr) \
    asm volatile("ldmatrix.sync.aligned.m8n8.x4.shared.b16 {%0,%1,%2,%3}, [%4];" \
        : "=r"(R0),"=r"(R1),"=r"(R2),"=r"(R3) : "r"(addr))

__device__ __forceinline__ void mma16816(float* c, uint32_t a0, uint32_t a1,
                                         uint32_t a2, uint32_t a3,
                                         uint32_t b0, uint32_t b1) {
    asm volatile(
        "mma.sync.aligned.m16n8k16.row.col.f32.bf16.bf16.f32 "
        "{%0,%1,%2,%3}, {%4,%5,%6,%7}, {%8,%9}, {%0,%1,%2,%3};"
        : "+f"(c[0]), "+f"(c[1]), "+f"(c[2]), "+f"(c[3])
        : "r"(a0), "r"(a1), "r"(a2), "r"(a3), "r"(b0), "r"(b1));
}

// one k16 step over a warp tile of MT*16 x 32 (4 n8-tiles), split-bf16 3-pass
template<int MT>
__device__ __forceinline__ void wmma_step(float (*acc)[4][4],
    uint32_t aHb, uint32_t aLb, uint32_t bHb, uint32_t bLb,
    int mrow0, int ncol0, int k0, int lane)
{
    uint32_t aH[MT][4], aL[MT][4];
    #pragma unroll
    for (int mi = 0; mi < MT; mi++) {
        uint32_t off = ((uint32_t)(mrow0 + mi*16 + (lane & 15))*40u + (uint32_t)k0 + ((lane >> 4) << 3)) * 2u;
        LDSM4(aH[mi][0], aH[mi][1], aH[mi][2], aH[mi][3], aHb + off);
        LDSM4(aL[mi][0], aL[mi][1], aL[mi][2], aL[mi][3], aLb + off);
    }
    uint32_t bHf[4][2], bLf[4][2];
    int j = lane >> 3;
    #pragma unroll
    for (int p = 0; p < 2; p++) {
        uint32_t off = ((uint32_t)(ncol0 + p*16 + ((j >> 1) << 3) + (lane & 7))*40u + (uint32_t)k0 + ((j & 1) << 3)) * 2u;
        uint32_t r0, r1, r2, r3;
        LDSM4(r0, r1, r2, r3, bHb + off);
        bHf[p*2][0] = r0; bHf[p*2][1] = r1; bHf[p*2+1][0] = r2; bHf[p*2+1][1] = r3;
        LDSM4(r0, r1, r2, r3, bLb + off);
        bLf[p*2][0] = r0; bLf[p*2][1] = r1; bLf[p*2+1][0] = r2; bLf[p*2+1][1] = r3;
    }
    #pragma unroll
    for (int mi = 0; mi < MT; mi++)
        #pragma unroll
        for (int nj = 0; nj < 4; nj++) {
            mma16816(acc[mi][nj], aH[mi][0], aH[mi][1], aH[mi][2], aH[mi][3], bHf[nj][0], bHf[nj][1]);
            mma16816(acc[mi][nj], aH[mi][0], aH[mi][1], aH[mi][2], aH[mi][3], bLf[nj][0], bLf[nj][1]);
            mma16816(acc[mi][nj], aL[mi][0], aL[mi][1], aL[mi][2], aL[mi][3], bHf[nj][0], bHf[nj][1]);
        }
}

// 4 n8-frags (32 cols) from smem tile (stride 40), frag fi covers cols n0_+fi*8
__device__ __forceinline__ void ldB32(uint32_t (*bf)[2], uint32_t base, int n0_, int k0, int lane) {
    int j = lane >> 3;
    #pragma unroll
    for (int p = 0; p < 2; p++) {
        uint32_t off = ((uint32_t)(n0_ + p*16 + ((j >> 1) << 3) + (lane & 7))*40u + (uint32_t)k0 + ((j & 1) << 3)) * 2u;
        uint32_t r0, r1, r2, r3;
        LDSM4(r0, r1, r2, r3, base + off);
        bf[p*2][0] = r0; bf[p*2][1] = r1; bf[p*2+1][0] = r2; bf[p*2+1][1] = r3;
    }
}

// load nrows x 32 bf16 chunk into smem tile (stride 40 elems) via cp.async
__device__ __forceinline__ void ld_tile32(uint32_t sdst, const bf16* g, size_t rstride, int nrows) {
    int tid = threadIdx.x;
    int tot = nrows * 4;
    for (int u = tid; u < tot; u += 256) {
        int r = u >> 2, c = u & 3;
        uint32_t dst = sdst + (uint32_t)(r*80 + c*16);
        const bf16* src = g + (size_t)r * rstride + (c << 3);
        asm volatile("cp.async.cg.shared.global [%0], [%1], 16;" :: "r"(dst), "l"(src) : "memory");
    }
}
#define CPA_COMMIT() asm volatile("cp.async.commit_group;" ::: "memory")
#define CPA_WAIT1()  asm volatile("cp.async.wait_group 1;" ::: "memory")
#define CPA_WAIT0()  asm volatile("cp.async.wait_group 0;" ::: "memory")

__device__ __forceinline__ void split2(float v, bf16& h, bf16& l) {
    h = __float2bfloat16(v);
    l = __float2bfloat16(v - __bfloat162float(h));
}
__device__ __forceinline__ uint32_t pack2(bf16 a, bf16 b) {
    return (uint32_t)__bfloat16_as_ushort(a) | ((uint32_t)__bfloat16_as_ushort(b) << 16);
}
__device__ __forceinline__ uint32_t packhi2(float a, float b) {
    return (uint32_t)__bfloat16_as_ushort(__float2bfloat16(a))
         | ((uint32_t)__bfloat16_as_ushort(__float2bfloat16(b)) << 16);
}
__device__ __forceinline__ uint32_t packlo2(float a, float b) {
    bf16 ha = __float2bfloat16(a), hb = __float2bfloat16(b);
    bf16 la = __float2bfloat16(a - __bfloat162float(ha));
    bf16 lb = __float2bfloat16(b - __bfloat162float(hb));
    return pack2(la, lb);
}

// ============================================================
// fp32 -> bf16 hi/lo split conversion. n4 = n/4
// ============================================================
__device__ __forceinline__ void conv_body(const float* __restrict__ s,
                                          bf16* __restrict__ h,
                                          bf16* __restrict__ l, int i) {
    float4 v = ((const float4*)s)[i];
    bf16 h0, h1, h2, h3, l0, l1, l2, l3;
    split2(v.x, h0, l0); split2(v.y, h1, l1); split2(v.z, h2, l2); split2(v.w, h3, l3);
    uint2 hp, lp;
    hp.x = pack2(h0, h1); hp.y = pack2(h2, h3);
    lp.x = pack2(l0, l1); lp.y = pack2(l2, l3);
    ((uint2*)h)[i] = hp;
    ((uint2*)l)[i] = lp;
}
__global__ void conv_kernel(const float* __restrict__ s, bf16* __restrict__ h,
                            bf16* __restrict__ l, int n4) {
    int i = blockIdx.x * 256 + threadIdx.x;
    if (i >= n4) return;
    conv_body(s, h, l, i);
}
__global__ void convW_kernel(const float* __restrict__ s0, bf16* __restrict__ h0,
                             bf16* __restrict__ l0,
                             const float* __restrict__ s1, bf16* __restrict__ h1,
                             bf16* __restrict__ l1, int n4) {
    int i = blockIdx.x * 256 + threadIdx.x;
    if (i >= n4) return;
    if (blockIdx.y == 0) conv_body(s0, h0, l0, i);
    else                 conv_body(s1, h1, l1, i);
}

// ============================================================
// proj: 128x128 tile of (xt @ W^T + b) via warp mma. grid(8,32,4) block 256
// ============================================================
__global__ void __launch_bounds__(256) proj_mm(
    const float* __restrict__ b0, const float* __restrict__ b1,
    const float* __restrict__ b2, const float* __restrict__ b3)
{
    extern __shared__ uint8_t dyn[];
    uint32_t sb = s2u(dyn);
    int tid = threadIdx.x, wid = tid >> 5, lane = tid & 31;

    int w = blockIdx.z;
    const bf16* WHp = (w==0)?WqH:(w==1)?WkH:(w==2)?WvH:WcH;
    const bf16* WLp = (w==0)?WqL:(w==1)?WkL:(w==2)?WvL:WcL;
    const float* bias = (w==0)?b0:(w==1)?b1:(w==2)?b2:b3;

    int m0 = blockIdx.y * 128, n0 = blockIdx.x * 128;
    int b_ = m0 >> 10, i0 = m0 & 1023;

    const bf16* aH = XH + (size_t)(b_*SS + i0 + 1)*EE;
    const bf16* aL = XL + (size_t)(b_*SS + i0 + 1)*EE;
    const bf16* bH = WHp + (size_t)n0*EE;
    const bf16* bL = WLp + (size_t)n0*EE;

    float acc[4][4][4] = {};
    int wm = wid & 1, wn = wid >> 1;
    int mrow0 = wm*64, ncol0 = wn*32;

    ld_tile32(sb,         aH, EE, 128);
    ld_tile32(sb + 10240, aL, EE, 128);
    ld_tile32(sb + 20480, bH, EE, 128);
    ld_tile32(sb + 30720, bL, EE, 128);
    CPA_COMMIT();
    int buf = 0;
    for (int ch = 0; ch < 32; ch++) {
        if (ch + 1 < 32) {
            uint32_t nb = sb + (buf^1)*40960;
            int kt = (ch + 1) * 32;
            ld_tile32(nb,         aH + kt, EE, 128);
            ld_tile32(nb + 10240, aL + kt, EE, 128);
            ld_tile32(nb + 20480, bH + kt, EE, 128);
            ld_tile32(nb + 30720, bL + kt, EE, 128);
            CPA_COMMIT();
            CPA_WAIT1();
        } else CPA_WAIT0();
        __syncthreads();
        uint32_t base = sb + buf*40960;
        wmma_step<4>(acc, base, base+10240, base+20480, base+30720, mrow0, ncol0, 0,  lane);
        wmma_step<4>(acc, base, base+10240, base+20480, base+30720, mrow0, ncol0, 16, lane);
        __syncthreads();
        buf ^= 1;
    }

    int rbase = mrow0 + (lane >> 2);
    int cbase = ncol0 + (lane & 3)*2;
    #pragma unroll
    for (int mi = 0; mi < 4; mi++)
        #pragma unroll
        for (int half = 0; half < 2; half++) {
            int i = i0 + rbase + mi*16 + half*8;
            #pragma unroll
            for (int nj = 0; nj < 4; nj++) {
                int col = n0 + cbase + nj*8;
                int h2 = col >> 6, d2 = col & 63;
                float v0 = acc[mi][nj][half*2]   + bias[col];
                float v1 = acc[mi][nj][half*2+1] + bias[col+1];
                bf16 h0v, l0v, h1v, l1v;
                split2(v0, h0v, l0v); split2(v1, h1v, l1v);
                size_t qi = ((size_t)(b_*HH + h2)*SQ + i)*DH + d2;
                size_t ti = ((size_t)(b_*HH + h2)*DH + d2)*SQ + i;
                if (w == 0) {
                    *(float2*)&QS[qi] = make_float2(v0, v1);
                    *(uint32_t*)&QH[qi] = pack2(h0v, h1v);
                    *(uint32_t*)&QL[qi] = pack2(l0v, l1v);
                } else if (w == 1) {
                    *(float2*)&KS[qi] = make_float2(v0, v1);
                    *(uint32_t*)&KH[qi] = pack2(h0v, h1v);
                    *(uint32_t*)&KL[qi] = pack2(l0v, l1v);
                } else if (w == 2) {
                    *(float2*)&VS[qi] = make_float2(v0, v1);
                    VTH[ti] = h0v;      VTL[ti] = l0v;
                    VTH[ti + SQ] = h1v; VTL[ti + SQ] = l1v;
                } else {
                    CPTH[ti] = h0v;      CPTL[ti] = l0v;
                    CPTH[ti + SQ] = h1v; CPTL[ti + SQ] = l1v;
                }
            }
        }
}

// ============================================================
// fused attention: per (m-block 128 rows, bh): S=QK^T -> raw l to attn,
// dual online softmax in regs, O1 += P1@V, O2 += P2@CP. grid(8, 64) block 256
// smem: Q 40960 + 2 x 61440 = 163840
// ============================================================
__global__ void __launch_bounds__(256) fused_attn(float* __restrict__ attn)
{
    extern __shared__ uint8_t dyn[];
    uint32_t sQ = s2u(dyn);
    uint32_t sT = sQ + 40960;            // two 61440 buffers
    int tid = threadIdx.x, wid = tid >> 5, lane = tid & 31;
    int bh = blockIdx.y;
    int m0 = blockIdx.x * 128;
    int mrow0 = wid * 16;
    int g = lane >> 2, tig = lane & 3;
    int r0 = mrow0 + g, r1 = r0 + 8;     // warp-local rows
    int gr0 = m0 + r0, gr1 = m0 + r1;    // block rows

    // per-row constants
    float qn0 = QN2[(size_t)bh*SQ + gr0], qn1 = QN2[(size_t)bh*SQ + gr1];
    float cn = CN2[bh];
    float sc0 = rsqrtf(64.0f * qn0), sc1r = rsqrtf(64.0f * qn1);
    float rr0 = rsqrtf(qn0 * cn), rr1 = rsqrtf(qn1 * cn);

    float* attnb = attn + (size_t)bh*SQ*SQ;
    const float* cqrow = CQg + (size_t)bh*SQ;

    // static Q tile (128x64 hi/lo)
    {
        const bf16* qh = QH + (size_t)bh*SQ*DH + (size_t)m0*DH;
        const bf16* ql = QL + (size_t)bh*SQ*DH + (size_t)m0*DH;
        ld_tile32(sQ,         qh,      DH, 128);
        ld_tile32(sQ + 10240, qh + 32, DH, 128);
        ld_tile32(sQ + 20480, ql,      DH, 128);
        ld_tile32(sQ + 30720, ql + 32, DH, 128);
        CPA_COMMIT();
    }

    // j-tile loader
    #define FLOAD(bb, jt) do { \
        int j0_ = (jt) * 64; \
        const bf16* kh_ = KH + (size_t)bh*SQ*DH + (size_t)j0_*DH; \
        const bf16* kl_ = KL + (size_t)bh*SQ*DH + (size_t)j0_*DH; \
        const bf16* vh_ = VTH + (size_t)bh*DH*SQ + j0_; \
        const bf16* vl_ = VTL + (size_t)bh*DH*SQ + j0_; \
        const bf16* ph_ = CPTH + (size_t)bh*DH*SQ + j0_; \
        const bf16* pl_ = CPTL + (size_t)bh*DH*SQ + j0_; \
        ld_tile32((bb),        kh_,      DH, 64); \
        ld_tile32((bb)+5120,   kh_ + 32, DH, 64); \
        ld_tile32((bb)+10240,  kl_,      DH, 64); \
        ld_tile32((bb)+15360,  kl_ + 32, DH, 64); \
        ld_tile32((bb)+20480,  vh_,      SQ, 64); \
        ld_tile32((bb)+25600,  vh_ + 32, SQ, 64); \
        ld_tile32((bb)+30720,  vl_,      SQ, 64); \
        ld_tile32((bb)+35840,  vl_ + 32, SQ, 64); \
        ld_tile32((bb)+40960,  ph_,      SQ, 64); \
        ld_tile32((bb)+46080,  ph_ + 32, SQ, 64); \
        ld_tile32((bb)+51200,  pl_,      SQ, 64); \
        ld_tile32((bb)+56320,  pl_ + 32, SQ, 64); \
        CPA_COMMIT(); \
    } while (0)

    float O1[8][4] = {}, O2[8][4] = {};
    float m1_0 = -1e30f, m1_1 = -1e30f, m2_0 = -1e30f, m2_1 = -1e30f;
    float s1_0 = 0.f, s1_1 = 0.f, s2_0 = 0.f, s2_1 = 0.f;

    FLOAD(sT, 0);
    int buf = 0;
    for (int jt = 0; jt < 16; jt++) {
        if (jt + 1 < 16) { FLOAD(sT + (buf^1)*61440, jt + 1); CPA_WAIT1(); }
        else CPA_WAIT0();
        __syncthreads();
        uint32_t bb = sT + buf*61440;
        int j0 = jt * 64;

        // ---- S = Q K^T  (16 x 64 per warp, 3-pass split bf16) ----
        float S[8][4] = {};
        #pragma unroll
        for (int kk = 0; kk < 64; kk += 16) {
            int cch = kk >> 5, k0 = kk & 16;
            uint32_t aQH = sQ + cch*10240;
            uint32_t aQL = sQ + 20480 + cch*10240;
            uint32_t a0, a1, a2, a3, e0, e1, e2, e3;
            uint32_t offA = ((uint32_t)(mrow0 + (lane & 15))*40u + (uint32_t)k0 + ((lane >> 4) << 3)) * 2u;
            LDSM4(a0, a1, a2, a3, aQH + offA);
            LDSM4(e0, e1, e2, e3, aQL + offA);
            uint32_t bHf[4][2], bLf[4][2], bHf2[4][2], bLf2[4][2];
            uint32_t kbH = bb + cch*5120, kbL = bb + 10240 + cch*5120;
            ldB32(bHf,  kbH, 0,  k0, lane);
            ldB32(bHf2, kbH, 32, k0, lane);
            ldB32(bLf,  kbL, 0,  k0, lane);
            ldB32(bLf2, kbL, 32, k0, lane);
            #pragma unroll
            for (int f = 0; f < 4; f++) {
                mma16816(S[f], a0, a1, a2, a3, bHf[f][0], bHf[f][1]);
                mma16816(S[f], a0, a1, a2, a3, bLf[f][0], bLf[f][1]);
                mma16816(S[f], e0, e1, e2, e3, bHf[f][0], bHf[f][1]);
                mma16816(S[f+4], a0, a1, a2, a3, bHf2[f][0], bHf2[f][1]);
                mma16816(S[f+4], a0, a1, a2, a3, bLf2[f][0], bLf2[f][1]);
                mma16816(S[f+4], e0, e1, e2, e3, bHf2[f][0], bHf2[f][1]);
            }
        }

        // ---- scale to l, store raw, track maxes ----
        float cqv[8][2];
        float lmax0 = -1e30f, lmax1 = -1e30f, l2max0 = -1e30f, l2max1 = -1e30f;
        #pragma unroll
        for (int f = 0; f < 8; f++) {
            int col = j0 + f*8 + tig*2;
            float2 cq = *(const float2*)&cqrow[col];
            cqv[f][0] = cq.x; cqv[f][1] = cq.y;
            S[f][0] *= sc0;  S[f][1] *= sc0;
            S[f][2] *= sc1r; S[f][3] *= sc1r;
            *(float2*)&attnb[(size_t)gr0*SQ + col] = make_float2(S[f][0], S[f][1]);
            *(float2*)&attnb[(size_t)gr1*SQ + col] = make_float2(S[f][2], S[f][3]);
            lmax0 = fmaxf(lmax0, fmaxf(S[f][0], S[f][1]));
            lmax1 = fmaxf(lmax1, fmaxf(S[f][2], S[f][3]));
            l2max0 = fmaxf(l2max0, fmaxf(S[f][0]*cq.x*rr0, S[f][1]*cq.y*rr0));
            l2max1 = fmaxf(l2max1, fmaxf(S[f][2]*cq.x*rr1, S[f][3]*cq.y*rr1));
        }
        #pragma unroll
        for (int o = 1; o <= 2; o <<= 1) {
            lmax0  = fmaxf(lmax0,  __shfl_xor_sync(0xffffffffu, lmax0,  o));
            lmax1  = fmaxf(lmax1,  __shfl_xor_sync(0xffffffffu, lmax1,  o));
            l2max0 = fmaxf(l2max0, __shfl_xor_sync(0xffffffffu, l2max0, o));
            l2max1 = fmaxf(l2max1, __shfl_xor_sync(0xffffffffu, l2max1, o));
        }
        float m1n0 = fmaxf(m1_0, lmax0),  m1n1 = fmaxf(m1_1, lmax1);
        float m2n0 = fmaxf(m2_0, l2max0), m2n1 = fmaxf(m2_1, l2max1);
        float f10 = __expf(m1_0 - m1n0), f11 = __expf(m1_1 - m1n1);
        float f20 = __expf(m2_0 - m2n0), f21 = __expf(m2_1 - m2n1);
        m1_0 = m1n0; m1_1 = m1n1; m2_0 = m2n0; m2_1 = m2n1;
        #pragma unroll
        for (int f = 0; f < 8; f++) {
            O1[f][0] *= f10; O1[f][1] *= f10; O1[f][2] *= f11; O1[f][3] *= f11;
            O2[f][0] *= f20; O2[f][1] *= f20; O2[f][2] *= f21; O2[f][3] *= f21;
        }

        // ---- path 1: P1 = exp(l - m1), accumulate O1 += P1 @ V ----
        {
            uint32_t ph01[8], ph23[8], pl01[8], pl23[8];
            float ps0 = 0.f, ps1 = 0.f;
            #pragma unroll
            for (int f = 0; f < 8; f++) {
                float p0 = __expf(S[f][0] - m1n0), p1v = __expf(S[f][1] - m1n0);
                float p2v = __expf(S[f][2] - m1n1), p3v = __expf(S[f][3] - m1n1);
                ps0 += p0 + p1v; ps1 += p2v + p3v;
                ph01[f] = packhi2(p0, p1v);  pl01[f] = packlo2(p0, p1v);
                ph23[f] = packhi2(p2v, p3v); pl23[f] = packlo2(p2v, p3v);
            }
            #pragma unroll
            for (int o = 1; o <= 2; o <<= 1) {
                ps0 += __shfl_xor_sync(0xffffffffu, ps0, o);
                ps1 += __shfl_xor_sync(0xffffffffu, ps1, o);
            }
            s1_0 = s1_0 * f10 + ps0; s1_1 = s1_1 * f11 + ps1;
            #pragma unroll
            for (int kk = 0; kk < 64; kk += 16) {
                int cch = kk >> 5, k0 = kk & 16;
                int gp = kk >> 3;  // 2*g' : frag pair index
                uint32_t vbH = bb + 20480 + cch*5120, vbL = bb + 30720 + cch*5120;
                uint32_t bHf[4][2], bLf[4][2], bHf2[4][2], bLf2[4][2];
                ldB32(bHf,  vbH, 0,  k0, lane);
                ldB32(bHf2, vbH, 32, k0, lane);
                ldB32(bLf,  vbL, 0,  k0, lane);
                ldB32(bLf2, vbL, 32, k0, lane);
                uint32_t a0 = ph01[gp], a1 = ph23[gp], a2 = ph01[gp+1], a3 = ph23[gp+1];
                uint32_t e0 = pl01[gp], e1 = pl23[gp], e2 = pl01[gp+1], e3 = pl23[gp+1];
                #pragma unroll
                for (int f = 0; f < 4; f++) {
                    mma16816(O1[f], a0, a1, a2, a3, bHf[f][0], bHf[f][1]);
                    mma16816(O1[f], a0, a1, a2, a3, bLf[f][0], bLf[f][1]);
                    mma16816(O1[f], e0, e1, e2, e3, bHf[f][0], bHf[f][1]);
                    mma16816(O1[f+4], a0, a1, a2, a3, bHf2[f][0], bHf2[f][1]);
                    mma16816(O1[f+4], a0, a1, a2, a3, bLf2[f][0], bLf2[f][1]);
                    mma16816(O1[f+4], e0, e1, e2, e3, bHf2[f][0], bHf2[f][1]);
                }
            }
        }

        // ---- path 2: P2 = exp(l*cq*rr - m2), accumulate O2 += P2 @ CP ----
        {
            uint32_t ph01[8], ph23[8], pl01[8], pl23[8];
            float ps0 = 0.f, ps1 = 0.f;
            #pragma unroll
            for (int f = 0; f < 8; f++) {
                float p0 = __expf(S[f][0]*cqv[f][0]*rr0 - m2n0);
                float p1v = __expf(S[f][1]*cqv[f][1]*rr0 - m2n0);
                float p2v = __expf(S[f][2]*cqv[f][0]*rr1 - m2n1);
                float p3v = __expf(S[f][3]*cqv[f][1]*rr1 - m2n1);
                ps0 += p0 + p1v; ps1 += p2v + p3v;
                ph01[f] = packhi2(p0, p1v);  pl01[f] = packlo2(p0, p1v);
                ph23[f] = packhi2(p2v, p3v); pl23[f] = packlo2(p2v, p3v);
            }
            #pragma unroll
            for (int o = 1; o <= 2; o <<= 1) {
                ps0 += __shfl_xor_sync(0xffffffffu, ps0, o);
                ps1 += __shfl_xor_sync(0xffffffffu, ps1, o);
            }
            s2_0 = s2_0 * f20 + ps0; s2_1 = s2_1 * f21 + ps1;
            #pragma unroll
            for (int kk = 0; kk < 64; kk += 16) {
                int cch = kk >> 5, k0 = kk & 16;
                int gp = kk >> 3;
                uint32_t pbH = bb + 40960 + cch*5120, pbL = bb + 51200 + cch*5120;
                uint32_t bHf[4][2], bLf[4][2], bHf2[4][2], bLf2[4][2];
                ldB32(bHf,  pbH, 0,  k0, lane);
                ldB32(bHf2, pbH, 32, k0, lane);
                ldB32(bLf,  pbL, 0,  k0, lane);
                ldB32(bLf2, pbL, 32, k0, lane);
                uint32_t a0 = ph01[gp], a1 = ph23[gp], a2 = ph01[gp+1], a3 = ph23[gp+1];
                uint32_t e0 = pl01[gp], e1 = pl23[gp], e2 = pl01[gp+1], e3 = pl23[gp+1];
                #pragma unroll
                for (int f = 0; f < 4; f++) {
                    mma16816(O2[f], a0, a1, a2, a3, bHf[f][0], bHf[f][1]);
                    mma16816(O2[f], a0, a1, a2, a3, bLf[f][0], bLf[f][1]);
                    mma16816(O2[f], e0, e1, e2, e3, bHf[f][0], bHf[f][1]);
                    mma16816(O2[f+4], a0, a1, a2, a3, bHf2[f][0], bHf2[f][1]);
                    mma16816(O2[f+4], a0, a1, a2, a3, bLf2[f][0], bLf2[f][1]);
                    mma16816(O2[f+4], e0, e1, e2, e3, bHf2[f][0], bHf2[f][1]);
                }
            }
        }
        __syncthreads();
        buf ^= 1;
    }
    #undef FLOAD

    // ---- epilogue: values rows (tokens), stats for attn_fix ----
    int b_ = bh / HH, h_ = bh % HH;
    float is10 = 1.f/s1_0, is11 = 1.f/s1_1, is20 = 1.f/s2_0, is21 = 1.f/s2_1;
    size_t ob0 = (size_t)(b_*SS + 1 + gr0)*EE + h_*DH;
    size_t ob1 = (size_t)(b_*SS + 1 + gr1)*EE + h_*DH;
    #pragma unroll
    for (int f = 0; f < 8; f++) {
        int d = f*8 + tig*2;
        float v0 = O1[f][0]*is10 + O2[f][0]*is20;
        float v1 = O1[f][1]*is10 + O2[f][1]*is20;
        float v2 = O1[f][2]*is11 + O2[f][2]*is21;
        float v3 = O1[f][3]*is11 + O2[f][3]*is21;
        *(uint32_t*)&VALSH[ob0 + d] = packhi2(v0, v1);
        *(uint32_t*)&VALSL[ob0 + d] = packlo2(v0, v1);
        *(uint32_t*)&VALSH[ob1 + d] = packhi2(v2, v3);
        *(uint32_t*)&VALSL[ob1 + d] = packlo2(v2, v3);
    }
    if (tig == 0) {
        M1g[(size_t)bh*SQ + gr0] = m1_0; S1g[(size_t)bh*SQ + gr0] = is10;
        M1g[(size_t)bh*SQ + gr1] = m1_1; S1g[(size_t)bh*SQ + gr1] = is11;
    }
}

// ============================================================
// attn_fix: attn = exp(l - M)/S in place. one row per block.
// ============================================================
__global__ void attn_fix(float* __restrict__ attn) {
    int row = blockIdx.x;
    float m = M1g[row], si = S1g[row];
    float4* p = (float4*)(attn + (size_t)row*SQ);
    float4 v = p[threadIdx.x];
    v.x = __expf(v.x - m)*si;
    v.y = __expf(v.y - m)*si;
    v.z = __expf(v.z - m)*si;
    v.w = __expf(v.w - m)*si;
    p[threadIdx.x] = v;
}

// ============================================================
// out: VALS @ Wo^T + bo. grid(8,33), M guard at 4100
// ============================================================
__global__ void __launch_bounds__(256) out_mm(const float* __restrict__ bo,
                                             float* __restrict__ out)
{
    extern __shared__ uint8_t dyn[];
    uint32_t sb = s2u(dyn);
    int tid = threadIdx.x, wid = tid >> 5, lane = tid & 31;
    int m0 = blockIdx.y * 128, n0 = blockIdx.x * 128;

    const bf16* aH = VALSH + (size_t)m0*EE;
    const bf16* aL = VALSL + (size_t)m0*EE;
    const bf16* bH = WoH + (size_t)n0*EE;
    const bf16* bL = WoL + (size_t)n0*EE;

    float acc[4][4][4] = {};
    int wm = wid & 1, wn = wid >> 1;
    int mrow0 = wm*64, ncol0 = wn*32;

    ld_tile32(sb,         aH, EE, 128);
    ld_tile32(sb + 10240, aL, EE, 128);
    ld_tile32(sb + 20480, bH, EE, 128);
    ld_tile32(sb + 30720, bL, EE, 128);
    CPA_COMMIT();
    int buf = 0;
    for (int ch = 0; ch < 32; ch++) {
        if (ch + 1 < 32) {
            uint32_t nb = sb + (buf^1)*40960;
            int kt = (ch + 1) * 32;
            ld_tile32(nb,         aH + kt, EE, 128);
            ld_tile32(nb + 10240, aL + kt, EE, 128);
            ld_tile32(nb + 20480, bH + kt, EE, 128);
            ld_tile32(nb + 30720, bL + kt, EE, 128);
            CPA_COMMIT();
            CPA_WAIT1();
        } else CPA_WAIT0();
        __syncthreads();
        uint32_t base = sb + buf*40960;
        wmma_step<4>(acc, base, base+10240, base+20480, base+30720, mrow0, ncol0, 0,  lane);
        wmma_step<4>(acc, base, base+10240, base+20480, base+30720, mrow0, ncol0, 16, lane);
        __syncthreads();
        buf ^= 1;
    }

    int rbase = mrow0 + (lane >> 2);
    int cbase = ncol0 + (lane & 3)*2;
    #pragma unroll
    for (int mi = 0; mi < 4; mi++)
        #pragma unroll
        for (int half = 0; half < 2; half++) {
            int mr = m0 + rbase + mi*16 + half*8;
            if (mr >= MROWS_OUT) continue;
            #pragma unroll
            for (int nj = 0; nj < 4; nj++) {
                int col = n0 + cbase + nj*8;
                *(float2*)&out[(size_t)mr*EE + col] =
                    make_float2(acc[mi][nj][half*2] + bo[col],
                                acc[mi][nj][half*2+1] + bo[col+1]);
            }
        }
}

// ============================================================
// cls token projection + CN2. grid BH, block 64
// ============================================================
__global__ void clsproj_kernel(const float* __restrict__ x,
                               const float* __restrict__ Wq,
                               const float* __restrict__ bq) {
    int bh = blockIdx.x;
    int b_ = bh / HH, h_ = bh % HH;
    int d  = threadIdx.x;
    int j  = h_*DH + d;
    const float* xr = x  + (size_t)(b_*SS)*EE;
    const float* wr = Wq + (size_t)j*EE;
    float s = 0.f;
    for (int e = 0; e < EE; e += 4) {
        float4 xv = *(const float4*)(xr + e);
        float4 wv = *(const float4*)(wr + e);
        s += xv.x*wv.x + xv.y*wv.y + xv.z*wv.z + xv.w*wv.w;
    }
    s += bq[j];
    CVEC[bh*DH + d] = s;
    __shared__ float red[64];
    red[d] = s*s; __syncthreads();
    for (int o = 32; o > 0; o >>= 1) { if (d < o) red[d] += red[d+o]; __syncthreads(); }
    if (d == 0) CN2[bh] = fmaxf(red[0], EPSF);
}

// ============================================================
// per-row q stats: QN2 and CQ. grid BH*SQ/8, block 256
// ============================================================
__global__ void qstats_kernel() {
    int row  = blockIdx.x*8 + (threadIdx.x >> 5);
    int lane = threadIdx.x & 31;
    int bh   = row >> 10;
    const float* qr = QS   + (size_t)row*DH;
    const float* cv = CVEC + bh*DH;
    float n2 = 0.f, cq = 0.f;
    #pragma unroll
    for (int d = lane; d < DH; d += 32) {
        float qv = qr[d];
        n2 += qv*qv;
        cq += qv*cv[d];
    }
    #pragma unroll
    for (int o = 16; o > 0; o >>= 1) {
        n2 += __shfl_xor_sync(0xffffffffu, n2, o);
        cq += __shfl_xor_sync(0xffffffffu, cq, o);
    }
    if (lane == 0) { QN2[row] = fmaxf(n2, EPSF); CQg[row] = cq; }
}

// ============================================================
// cls path: ck softmax -> cls_out row (hi/lo into VALS). grid BH, block 256
// ============================================================
__global__ void cls_kernel() {
    int bh = blockIdx.x;
    int tid = threadIdx.x;
    const float* Kp = KS + (size_t)bh*SQ*DH;
    const float* Vp = VS + (size_t)bh*SQ*DH;
    __shared__ float p_s[SQ];
    __shared__ float red[256];
    __shared__ float c_s[DH];
    if (tid < DH) c_s[tid] = CVEC[bh*DH + tid];
    __syncthreads();

    float scale = rsqrtf(64.0f * CN2[bh]);
    float lo[4];
    #pragma unroll
    for (int p = 0; p < 4; p++) {
        int j = tid + p*256;
        const float* kr = Kp + (size_t)j*DH;
        float s = 0.f;
        #pragma unroll
        for (int d = 0; d < DH; d += 4) {
            float4 kv = *(const float4*)(kr + d);
            s += c_s[d]*kv.x + c_s[d+1]*kv.y + c_s[d+2]*kv.z + c_s[d+3]*kv.w;
        }
        lo[p] = s * scale;
    }
    float m = fmaxf(fmaxf(lo[0],lo[1]), fmaxf(lo[2],lo[3]));
    red[tid] = m; __syncthreads();
    #pragma unroll
    for (int o = 128; o > 0; o >>= 1) { if (tid < o) red[tid] = fmaxf(red[tid], red[tid+o]); __syncthreads(); }
    m = red[0]; __syncthreads();
    float e[4], s = 0.f;
    #pragma unroll
    for (int p = 0; p < 4; p++) { e[p] = __expf(lo[p] - m); s += e[p]; }
    red[tid] = s; __syncthreads();
    #pragma unroll
    for (int o = 128; o > 0; o >>= 1) { if (tid < o) red[tid] += red[tid+o]; __syncthreads(); }
    float inv = 1.0f / red[0]; __syncthreads();
    #pragma unroll
    for (int p = 0; p < 4; p++) p_s[tid + p*256] = e[p]*inv;
    __syncthreads();

    int d = tid & 63, g = tid >> 6;
    float acc = 0.f;
    for (int j = g*256; j < (g+1)*256; j++) acc += p_s[j] * Vp[(size_t)j*DH + d];
    red[tid] = acc; __syncthreads();
    if (g == 0) {
        float rsum = red[tid] + red[tid+64] + red[tid+128] + red[tid+192];
        int b_ = bh / HH, h_ = bh % HH;
        bf16 hi, lov; split2(rsum, hi, lov);
        size_t idx = (size_t)(b_*SS)*EE + h_*DH + d;
        VALSH[idx] = hi;
        VALSL[idx] = lov;
    }
}

extern "C" void kernel_launch(void* const* d_in, const int* in_sizes, int n_in,
                              void* d_out, int out_size) {
    const float* x  = (const float*)d_in[0];
    const float* Wq = (const float*)d_in[1];
    const float* bq = (const float*)d_in[2];
    const float* Wk = (const float*)d_in[3];
    const float* bk = (const float*)d_in[4];
    const float* Wv = (const float*)d_in[5];
    const float* bv = (const float*)d_in[6];
    const float* Wo = (const float*)d_in[7];
    const float* bo = (const float*)d_in[8];
    const float* Wc = (const float*)d_in[9];
    const float* bc = (const float*)d_in[10];

    float* out  = (float*)d_out;
    float* attn = out + (size_t)BB*SS*EE;

    cudaFuncSetAttribute(proj_mm,    cudaFuncAttributeMaxDynamicSharedMemorySize, 81920);
    cudaFuncSetAttribute(out_mm,     cudaFuncAttributeMaxDynamicSharedMemorySize, 81920);
    cudaFuncSetAttribute(fused_attn, cudaFuncAttributeMaxDynamicSharedMemorySize, 163840);

    bf16 *xh, *xl, *wqh, *wql, *wkh, *wkl, *wvh, *wvl, *wch, *wcl, *woh, *wol;
    cudaGetSymbolAddress((void**)&xh, XH);   cudaGetSymbolAddress((void**)&xl, XL);
    cudaGetSymbolAddress((void**)&wqh, WqH); cudaGetSymbolAddress((void**)&wql, WqL);
    cudaGetSymbolAddress((void**)&wkh, WkH); cudaGetSymbolAddress((void**)&wkl, WkL);
    cudaGetSymbolAddress((void**)&wvh, WvH); cudaGetSymbolAddress((void**)&wvl, WvL);
    cudaGetSymbolAddress((void**)&wch, WcH); cudaGetSymbolAddress((void**)&wcl, WcL);
    cudaGetSymbolAddress((void**)&woh, WoH); cudaGetSymbolAddress((void**)&wol, WoL);

    int nx4 = BB*SS*EE/4, nw4 = EE*EE/4;
    // 1: x conversion
    conv_kernel<<<(nx4+255)/256, 256>>>(x,  xh,  xl,  nx4);
    // 2: Wq + Wk
    convW_kernel<<<dim3((nw4+255)/256, 2), 256>>>(Wq, wqh, wql, Wk, wkh, wkl, nw4);
    // 3: Wv + Wc
    convW_kernel<<<dim3((nw4+255)/256, 2), 256>>>(Wv, wvh, wvl, Wc, wch, wcl, nw4);
    // 4: proj (ncu's launch #6 target)
    proj_mm<<<dim3(8,32,4), 256, 81920>>>(bq, bk, bv, bc);
    // 5: Wo conversion
    conv_kernel<<<(nw4+255)/256, 256>>>(Wo, woh, wol, nw4);
    // 6-7: cls projection + q stats
    clsproj_kernel<<<BH, 64>>>(x, Wq, bq);
    qstats_kernel<<<BH*SQ/8, 256>>>();
    // 8: fused attention (raw logits + values)
    fused_attn<<<dim3(8,BH), 256, 163840>>>(attn);
    // 9: attn normalization in place
    attn_fix<<<BH*SQ, 256>>>(attn);
    // 10: cls output row
    cls_kernel<<<BH, 256>>>();
    // 11: output projection
    out_mm<<<dim3(8,33), 256, 81920>>>(bo, out);
}

// round 8
// speedup vs baseline: 1.2308x; 1.0226x over previous
#include <cuda_runtime.h>
#include <cuda_bf16.h>
#include <cstdint>

#define BB 4
#define SS 1025
#define SQ 1024
#define EE 1024
#define HH 16
#define DH 64
#define BH (BB*HH)
#define EPSF 1e-5f
#define MROWS_OUT (BB*SS)     // 4100
#define MTILES_OUT 33         // 33*128 = 4224

typedef __nv_bfloat16 bf16;

// ---------------- device scratch (allocation-free) ----------------
__device__ float QS[BH*SQ*DH];          // fp32 q  (qstats)
__device__ float KS[BH*SQ*DH];          // fp32 k  (cls path)
__device__ float VS[BH*SQ*DH];          // fp32 v  (cls path)
__device__ bf16 XH[BB*SS*EE],  XL[BB*SS*EE];
__device__ bf16 WqH[EE*EE], WqL[EE*EE], WkH[EE*EE], WkL[EE*EE];
__device__ bf16 WvH[EE*EE], WvL[EE*EE], WcH[EE*EE], WcL[EE*EE];
__device__ bf16 WoH[EE*EE], WoL[EE*EE];
__device__ bf16 QH[BH*SQ*DH], QL[BH*SQ*DH], KH[BH*SQ*DH], KL[BH*SQ*DH];
__device__ bf16 VTH[BH*DH*SQ], VTL[BH*DH*SQ];        // V^T [bh][d][j]
__device__ bf16 CPTH[BH*DH*SQ], CPTL[BH*DH*SQ];      // cls_proj^T
__device__ bf16 VALSH[(size_t)MTILES_OUT*128*EE], VALSL[(size_t)MTILES_OUT*128*EE];
__device__ float CVEC[BH*DH];
__device__ float CN2[BH];
__device__ float QN2[BH*SQ];
__device__ float CQg[BH*SQ];
__device__ float M1g[BH*SQ];            // final row max (path 1)
__device__ float S1g[BH*SQ];            // 1/rowsum (path 1)

// ---------------- warp-mma helpers ----------------
__device__ __forceinline__ uint32_t s2u(const void* p) {
    uint32_t a;
    asm("{ .reg .u64 t; cvta.to.shared.u64 t, %1; cvt.u32.u64 %0, t; }" : "=r"(a) : "l"(p));
    return a;
}
#define LDSM4(R0,R1,R2,R3,addr) \
    asm volatile("ldmatrix.sync.aligned.m8n8.x4.shared.b16 {%0,%1,%2,%3}, [%4];" \
        : "=r"(R0),"=r"(R1),"=r"(R2),"=r"(R3) : "r"(addr))

__device__ __forceinline__ void mma16816(float* c, uint32_t a0, uint32_t a1,
                                         uint32_t a2, uint32_t a3,
                                         uint32_t b0, uint32_t b1) {
    asm volatile(
        "mma.sync.aligned.m16n8k16.row.col.f32.bf16.bf16.f32 "
        "{%0,%1,%2,%3}, {%4,%5,%6,%7}, {%8,%9}, {%0,%1,%2,%3};"
        : "+f"(c[0]), "+f"(c[1]), "+f"(c[2]), "+f"(c[3])
        : "r"(a0), "r"(a1), "r"(a2), "r"(a3), "r"(b0), "r"(b1));
}

// one k16 step over a warp tile of MT*16 x 32 (4 n8-tiles), split-bf16 3-pass.
// MMAs issued pass-by-pass so consecutive MMAs hit DIFFERENT accumulators
// (asm volatile blocks compiler reordering; RAW chains were the R7 stall).
template<int MT>
__device__ __forceinline__ void wmma_step(float (*acc)[4][4],
    uint32_t aHb, uint32_t aLb, uint32_t bHb, uint32_t bLb,
    int mrow0, int ncol0, int k0, int lane)
{
    uint32_t aH[MT][4], aL[MT][4];
    #pragma unroll
    for (int mi = 0; mi < MT; mi++) {
        uint32_t off = ((uint32_t)(mrow0 + mi*16 + (lane & 15))*40u + (uint32_t)k0 + ((lane >> 4) << 3)) * 2u;
        LDSM4(aH[mi][0], aH[mi][1], aH[mi][2], aH[mi][3], aHb + off);
        LDSM4(aL[mi][0], aL[mi][1], aL[mi][2], aL[mi][3], aLb + off);
    }
    uint32_t bHf[4][2], bLf[4][2];
    int j = lane >> 3;
    #pragma unroll
    for (int p = 0; p < 2; p++) {
        uint32_t off = ((uint32_t)(ncol0 + p*16 + ((j >> 1) << 3) + (lane & 7))*40u + (uint32_t)k0 + ((j & 1) << 3)) * 2u;
        uint32_t r0, r1, r2, r3;
        LDSM4(r0, r1, r2, r3, bHb + off);
        bHf[p*2][0] = r0; bHf[p*2][1] = r1; bHf[p*2+1][0] = r2; bHf[p*2+1][1] = r3;
        LDSM4(r0, r1, r2, r3, bLb + off);
        bLf[p*2][0] = r0; bLf[p*2][1] = r1; bLf[p*2+1][0] = r2; bLf[p*2+1][1] = r3;
    }
    // pass 1: hi*hi over all accumulators
    #pragma unroll
    for (int mi = 0; mi < MT; mi++)
        #pragma unroll
        for (int nj = 0; nj < 4; nj++)
            mma16816(acc[mi][nj], aH[mi][0], aH[mi][1], aH[mi][2], aH[mi][3], bHf[nj][0], bHf[nj][1]);
    // pass 2: hi*lo
    #pragma unroll
    for (int mi = 0; mi < MT; mi++)
        #pragma unroll
        for (int nj = 0; nj < 4; nj++)
            mma16816(acc[mi][nj], aH[mi][0], aH[mi][1], aH[mi][2], aH[mi][3], bLf[nj][0], bLf[nj][1]);
    // pass 3: lo*hi
    #pragma unroll
    for (int mi = 0; mi < MT; mi++)
        #pragma unroll
        for (int nj = 0; nj < 4; nj++)
            mma16816(acc[mi][nj], aL[mi][0], aL[mi][1], aL[mi][2], aL[mi][3], bHf[nj][0], bHf[nj][1]);
}

// 4 n8-frags (32 cols) from smem tile (stride 40), frag fi covers cols n0_+fi*8
__device__ __forceinline__ void ldB32(uint32_t (*bf)[2], uint32_t base, int n0_, int k0, int lane) {
    int j = lane >> 3;
    #pragma unroll
    for (int p = 0; p < 2; p++) {
        uint32_t off = ((uint32_t)(n0_ + p*16 + ((j >> 1) << 3) + (lane & 7))*40u + (uint32_t)k0 + ((j & 1) << 3)) * 2u;
        uint32_t r0, r1, r2, r3;
        LDSM4(r0, r1, r2, r3, base + off);
        bf[p*2][0] = r0; bf[p*2][1] = r1; bf[p*2+1][0] = r2; bf[p*2+1][1] = r3;
    }
}

// load nrows x 32 bf16 chunk into smem tile (stride 40 elems) via cp.async
__device__ __forceinline__ void ld_tile32(uint32_t sdst, const bf16* g, size_t rstride, int nrows) {
    int tid = threadIdx.x;
    int tot = nrows * 4;
    for (int u = tid; u < tot; u += 256) {
        int r = u >> 2, c = u & 3;
        uint32_t dst = sdst + (uint32_t)(r*80 + c*16);
        const bf16* src = g + (size_t)r * rstride + (c << 3);
        asm volatile("cp.async.cg.shared.global [%0], [%1], 16;" :: "r"(dst), "l"(src) : "memory");
    }
}
#define CPA_COMMIT() asm volatile("cp.async.commit_group;" ::: "memory")
#define CPA_WAIT1()  asm volatile("cp.async.wait_group 1;" ::: "memory")
#define CPA_WAIT0()  asm volatile("cp.async.wait_group 0;" ::: "memory")

__device__ __forceinline__ void split2(float v, bf16& h, bf16& l) {
    h = __float2bfloat16(v);
    l = __float2bfloat16(v - __bfloat162float(h));
}
__device__ __forceinline__ uint32_t pack2(bf16 a, bf16 b) {
    return (uint32_t)__bfloat16_as_ushort(a) | ((uint32_t)__bfloat16_as_ushort(b) << 16);
}
__device__ __forceinline__ uint32_t packhi2(float a, float b) {
    return (uint32_t)__bfloat16_as_ushort(__float2bfloat16(a))
         | ((uint32_t)__bfloat16_as_ushort(__float2bfloat16(b)) << 16);
}
__device__ __forceinline__ uint32_t packlo2(float a, float b) {
    bf16 ha = __float2bfloat16(a), hb = __float2bfloat16(b);
    bf16 la = __float2bfloat16(a - __bfloat162float(ha));
    bf16 lb = __float2bfloat16(b - __bfloat162float(hb));
    return pack2(la, lb);
}

// ============================================================
// fp32 -> bf16 hi/lo split conversion. n4 = n/4
// ============================================================
__device__ __forceinline__ void conv_body(const float* __restrict__ s,
                                          bf16* __restrict__ h,
                                          bf16* __restrict__ l, int i) {
    float4 v = ((const float4*)s)[i];
    bf16 h0, h1, h2, h3, l0, l1, l2, l3;
    split2(v.x, h0, l0); split2(v.y, h1, l1); split2(v.z, h2, l2); split2(v.w, h3, l3);
    uint2 hp, lp;
    hp.x = pack2(h0, h1); hp.y = pack2(h2, h3);
    lp.x = pack2(l0, l1); lp.y = pack2(l2, l3);
    ((uint2*)h)[i] = hp;
    ((uint2*)l)[i] = lp;
}
__global__ void conv_kernel(const float* __restrict__ s, bf16* __restrict__ h,
                            bf16* __restrict__ l, int n4) {
    int i = blockIdx.x * 256 + threadIdx.x;
    if (i >= n4) return;
    conv_body(s, h, l, i);
}
__global__ void convW_kernel(const float* __restrict__ s0, bf16* __restrict__ h0,
                             bf16* __restrict__ l0,
                             const float* __restrict__ s1, bf16* __restrict__ h1,
                             bf16* __restrict__ l1, int n4) {
    int i = blockIdx.x * 256 + threadIdx.x;
    if (i >= n4) return;
    if (blockIdx.y == 0) conv_body(s0, h0, l0, i);
    else                 conv_body(s1, h1, l1, i);
}

// ============================================================
// proj: 128x128 tile of (xt @ W^T + b) via warp mma. grid(8,32,4) block 256
// ============================================================
__global__ void __launch_bounds__(256) proj_mm(
    const float* __restrict__ b0, const float* __restrict__ b1,
    const float* __restrict__ b2, const float* __restrict__ b3)
{
    extern __shared__ uint8_t dyn[];
    uint32_t sb = s2u(dyn);
    int tid = threadIdx.x, wid = tid >> 5, lane = tid & 31;

    int w = blockIdx.z;
    const bf16* WHp = (w==0)?WqH:(w==1)?WkH:(w==2)?WvH:WcH;
    const bf16* WLp = (w==0)?WqL:(w==1)?WkL:(w==2)?WvL:WcL;
    const float* bias = (w==0)?b0:(w==1)?b1:(w==2)?b2:b3;

    int m0 = blockIdx.y * 128, n0 = blockIdx.x * 128;
    int b_ = m0 >> 10, i0 = m0 & 1023;

    const bf16* aH = XH + (size_t)(b_*SS + i0 + 1)*EE;
    const bf16* aL = XL + (size_t)(b_*SS + i0 + 1)*EE;
    const bf16* bH = WHp + (size_t)n0*EE;
    const bf16* bL = WLp + (size_t)n0*EE;

    float acc[4][4][4] = {};
    int wm = wid & 1, wn = wid >> 1;
    int mrow0 = wm*64, ncol0 = wn*32;

    ld_tile32(sb,         aH, EE, 128);
    ld_tile32(sb + 10240, aL, EE, 128);
    ld_tile32(sb + 20480, bH, EE, 128);
    ld_tile32(sb + 30720, bL, EE, 128);
    CPA_COMMIT();
    int buf = 0;
    for (int ch = 0; ch < 32; ch++) {
        if (ch + 1 < 32) {
            uint32_t nb = sb + (buf^1)*40960;
            int kt = (ch + 1) * 32;
            ld_tile32(nb,         aH + kt, EE, 128);
            ld_tile32(nb + 10240, aL + kt, EE, 128);
            ld_tile32(nb + 20480, bH + kt, EE, 128);
            ld_tile32(nb + 30720, bL + kt, EE, 128);
            CPA_COMMIT();
            CPA_WAIT1();
        } else CPA_WAIT0();
        __syncthreads();
        uint32_t base = sb + buf*40960;
        wmma_step<4>(acc, base, base+10240, base+20480, base+30720, mrow0, ncol0, 0,  lane);
        wmma_step<4>(acc, base, base+10240, base+20480, base+30720, mrow0, ncol0, 16, lane);
        __syncthreads();
        buf ^= 1;
    }

    int rbase = mrow0 + (lane >> 2);
    int cbase = ncol0 + (lane & 3)*2;
    #pragma unroll
    for (int mi = 0; mi < 4; mi++)
        #pragma unroll
        for (int half = 0; half < 2; half++) {
            int i = i0 + rbase + mi*16 + half*8;
            #pragma unroll
            for (int nj = 0; nj < 4; nj++) {
                int col = n0 + cbase + nj*8;
                int h2 = col >> 6, d2 = col & 63;
                float v0 = acc[mi][nj][half*2]   + bias[col];
                float v1 = acc[mi][nj][half*2+1] + bias[col+1];
                bf16 h0v, l0v, h1v, l1v;
                split2(v0, h0v, l0v); split2(v1, h1v, l1v);
                size_t qi = ((size_t)(b_*HH + h2)*SQ + i)*DH + d2;
                size_t ti = ((size_t)(b_*HH + h2)*DH + d2)*SQ + i;
                if (w == 0) {
                    *(float2*)&QS[qi] = make_float2(v0, v1);
                    *(uint32_t*)&QH[qi] = pack2(h0v, h1v);
                    *(uint32_t*)&QL[qi] = pack2(l0v, l1v);
                } else if (w == 1) {
                    *(float2*)&KS[qi] = make_float2(v0, v1);
                    *(uint32_t*)&KH[qi] = pack2(h0v, h1v);
                    *(uint32_t*)&KL[qi] = pack2(l0v, l1v);
                } else if (w == 2) {
                    *(float2*)&VS[qi] = make_float2(v0, v1);
                    VTH[ti] = h0v;      VTL[ti] = l0v;
                    VTH[ti + SQ] = h1v; VTL[ti + SQ] = l1v;
                } else {
                    CPTH[ti] = h0v;      CPTL[ti] = l0v;
                    CPTH[ti + SQ] = h1v; CPTL[ti + SQ] = l1v;
                }
            }
        }
}

// ============================================================
// fused attention: per (m-block 128 rows, bh): S=QK^T -> raw l to attn,
// dual online softmax in regs, O1 += P1@V, O2 += P2@CP. grid(8, 64) block 256
// smem: Q 40960 + 2 x 61440 = 163840
// ============================================================
__global__ void __launch_bounds__(256) fused_attn(float* __restrict__ attn)
{
    extern __shared__ uint8_t dyn[];
    uint32_t sQ = s2u(dyn);
    uint32_t sT = sQ + 40960;            // two 61440 buffers
    int tid = threadIdx.x, wid = tid >> 5, lane = tid & 31;
    int bh = blockIdx.y;
    int m0 = blockIdx.x * 128;
    int mrow0 = wid * 16;
    int g = lane >> 2, tig = lane & 3;
    int r0 = mrow0 + g, r1 = r0 + 8;     // warp-local rows
    int gr0 = m0 + r0, gr1 = m0 + r1;    // block rows

    // per-row constants
    float qn0 = QN2[(size_t)bh*SQ + gr0], qn1 = QN2[(size_t)bh*SQ + gr1];
    float cn = CN2[bh];
    float sc0 = rsqrtf(64.0f * qn0), sc1r = rsqrtf(64.0f * qn1);
    float rr0 = rsqrtf(qn0 * cn), rr1 = rsqrtf(qn1 * cn);

    float* attnb = attn + (size_t)bh*SQ*SQ;
    const float* cqrow = CQg + (size_t)bh*SQ;

    // static Q tile (128x64 hi/lo)
    {
        const bf16* qh = QH + (size_t)bh*SQ*DH + (size_t)m0*DH;
        const bf16* ql = QL + (size_t)bh*SQ*DH + (size_t)m0*DH;
        ld_tile32(sQ,         qh,      DH, 128);
        ld_tile32(sQ + 10240, qh + 32, DH, 128);
        ld_tile32(sQ + 20480, ql,      DH, 128);
        ld_tile32(sQ + 30720, ql + 32, DH, 128);
        CPA_COMMIT();
    }

    // j-tile loader
    #define FLOAD(bb, jt) do { \
        int j0_ = (jt) * 64; \
        const bf16* kh_ = KH + (size_t)bh*SQ*DH + (size_t)j0_*DH; \
        const bf16* kl_ = KL + (size_t)bh*SQ*DH + (size_t)j0_*DH; \
        const bf16* vh_ = VTH + (size_t)bh*DH*SQ + j0_; \
        const bf16* vl_ = VTL + (size_t)bh*DH*SQ + j0_; \
        const bf16* ph_ = CPTH + (size_t)bh*DH*SQ + j0_; \
        const bf16* pl_ = CPTL + (size_t)bh*DH*SQ + j0_; \
        ld_tile32((bb),        kh_,      DH, 64); \
        ld_tile32((bb)+5120,   kh_ + 32, DH, 64); \
        ld_tile32((bb)+10240,  kl_,      DH, 64); \
        ld_tile32((bb)+15360,  kl_ + 32, DH, 64); \
        ld_tile32((bb)+20480,  vh_,      SQ, 64); \
        ld_tile32((bb)+25600,  vh_ + 32, SQ, 64); \
        ld_tile32((bb)+30720,  vl_,      SQ, 64); \
        ld_tile32((bb)+35840,  vl_ + 32, SQ, 64); \
        ld_tile32((bb)+40960,  ph_,      SQ, 64); \
        ld_tile32((bb)+46080,  ph_ + 32, SQ, 64); \
        ld_tile32((bb)+51200,  pl_,      SQ, 64); \
        ld_tile32((bb)+56320,  pl_ + 32, SQ, 64); \
        CPA_COMMIT(); \
    } while (0)

    float O1[8][4] = {}, O2[8][4] = {};
    float m1_0 = -1e30f, m1_1 = -1e30f, m2_0 = -1e30f, m2_1 = -1e30f;
    float s1_0 = 0.f, s1_1 = 0.f, s2_0 = 0.f, s2_1 = 0.f;

    FLOAD(sT, 0);
    int buf = 0;
    for (int jt = 0; jt < 16; jt++) {
        if (jt + 1 < 16) { FLOAD(sT + (buf^1)*61440, jt + 1); CPA_WAIT1(); }
        else CPA_WAIT0();
        __syncthreads();
        uint32_t bb = sT + buf*61440;
        int j0 = jt * 64;

        // ---- S = Q K^T  (16 x 64 per warp, 3-pass split, pass-ordered) ----
        float S[8][4] = {};
        #pragma unroll
        for (int kk = 0; kk < 64; kk += 16) {
            int cch = kk >> 5, k0 = kk & 16;
            uint32_t aQH = sQ + cch*10240;
            uint32_t aQL = sQ + 20480 + cch*10240;
            uint32_t a0, a1, a2, a3, e0, e1, e2, e3;
            uint32_t offA = ((uint32_t)(mrow0 + (lane & 15))*40u + (uint32_t)k0 + ((lane >> 4) << 3)) * 2u;
            LDSM4(a0, a1, a2, a3, aQH + offA);
            LDSM4(e0, e1, e2, e3, aQL + offA);
            uint32_t bHf[4][2], bLf[4][2], bHf2[4][2], bLf2[4][2];
            uint32_t kbH = bb + cch*5120, kbL = bb + 10240 + cch*5120;
            ldB32(bHf,  kbH, 0,  k0, lane);
            ldB32(bHf2, kbH, 32, k0, lane);
            ldB32(bLf,  kbL, 0,  k0, lane);
            ldB32(bLf2, kbL, 32, k0, lane);
            #pragma unroll
            for (int f = 0; f < 4; f++) {
                mma16816(S[f],   a0, a1, a2, a3, bHf[f][0],  bHf[f][1]);
                mma16816(S[f+4], a0, a1, a2, a3, bHf2[f][0], bHf2[f][1]);
            }
            #pragma unroll
            for (int f = 0; f < 4; f++) {
                mma16816(S[f],   a0, a1, a2, a3, bLf[f][0],  bLf[f][1]);
                mma16816(S[f+4], a0, a1, a2, a3, bLf2[f][0], bLf2[f][1]);
            }
            #pragma unroll
            for (int f = 0; f < 4; f++) {
                mma16816(S[f],   e0, e1, e2, e3, bHf[f][0],  bHf[f][1]);
                mma16816(S[f+4], e0, e1, e2, e3, bHf2[f][0], bHf2[f][1]);
            }
        }

        // ---- scale to l, store raw, track maxes ----
        float cqv[8][2];
        float lmax0 = -1e30f, lmax1 = -1e30f, l2max0 = -1e30f, l2max1 = -1e30f;
        #pragma unroll
        for (int f = 0; f < 8; f++) {
            int col = j0 + f*8 + tig*2;
            float2 cq = *(const float2*)&cqrow[col];
            cqv[f][0] = cq.x; cqv[f][1] = cq.y;
            S[f][0] *= sc0;  S[f][1] *= sc0;
            S[f][2] *= sc1r; S[f][3] *= sc1r;
            *(float2*)&attnb[(size_t)gr0*SQ + col] = make_float2(S[f][0], S[f][1]);
            *(float2*)&attnb[(size_t)gr1*SQ + col] = make_float2(S[f][2], S[f][3]);
            lmax0 = fmaxf(lmax0, fmaxf(S[f][0], S[f][1]));
            lmax1 = fmaxf(lmax1, fmaxf(S[f][2], S[f][3]));
            l2max0 = fmaxf(l2max0, fmaxf(S[f][0]*cq.x*rr0, S[f][1]*cq.y*rr0));
            l2max1 = fmaxf(l2max1, fmaxf(S[f][2]*cq.x*rr1, S[f][3]*cq.y*rr1));
        }
        #pragma unroll
        for (int o = 1; o <= 2; o <<= 1) {
            lmax0  = fmaxf(lmax0,  __shfl_xor_sync(0xffffffffu, lmax0,  o));
            lmax1  = fmaxf(lmax1,  __shfl_xor_sync(0xffffffffu, lmax1,  o));
            l2max0 = fmaxf(l2max0, __shfl_xor_sync(0xffffffffu, l2max0, o));
            l2max1 = fmaxf(l2max1, __shfl_xor_sync(0xffffffffu, l2max1, o));
        }
        float m1n0 = fmaxf(m1_0, lmax0),  m1n1 = fmaxf(m1_1, lmax1);
        float m2n0 = fmaxf(m2_0, l2max0), m2n1 = fmaxf(m2_1, l2max1);
        float f10 = __expf(m1_0 - m1n0), f11 = __expf(m1_1 - m1n1);
        float f20 = __expf(m2_0 - m2n0), f21 = __expf(m2_1 - m2n1);
        m1_0 = m1n0; m1_1 = m1n1; m2_0 = m2n0; m2_1 = m2n1;
        #pragma unroll
        for (int f = 0; f < 8; f++) {
            O1[f][0] *= f10; O1[f][1] *= f10; O1[f][2] *= f11; O1[f][3] *= f11;
            O2[f][0] *= f20; O2[f][1] *= f20; O2[f][2] *= f21; O2[f][3] *= f21;
        }

        // ---- path 1: P1 = exp(l - m1), accumulate O1 += P1 @ V ----
        {
            uint32_t ph01[8], ph23[8], pl01[8], pl23[8];
            float ps0 = 0.f, ps1 = 0.f;
            #pragma unroll
            for (int f = 0; f < 8; f++) {
                float p0 = __expf(S[f][0] - m1n0), p1v = __expf(S[f][1] - m1n0);
                float p2v = __expf(S[f][2] - m1n1), p3v = __expf(S[f][3] - m1n1);
                ps0 += p0 + p1v; ps1 += p2v + p3v;
                ph01[f] = packhi2(p0, p1v);  pl01[f] = packlo2(p0, p1v);
                ph23[f] = packhi2(p2v, p3v); pl23[f] = packlo2(p2v, p3v);
            }
            #pragma unroll
            for (int o = 1; o <= 2; o <<= 1) {
                ps0 += __shfl_xor_sync(0xffffffffu, ps0, o);
                ps1 += __shfl_xor_sync(0xffffffffu, ps1, o);
            }
            s1_0 = s1_0 * f10 + ps0; s1_1 = s1_1 * f11 + ps1;
            #pragma unroll
            for (int kk = 0; kk < 64; kk += 16) {
                int cch = kk >> 5, k0 = kk & 16;
                int gp = kk >> 3;  // 2*g' : frag pair index
                uint32_t vbH = bb + 20480 + cch*5120, vbL = bb + 30720 + cch*5120;
                uint32_t bHf[4][2], bLf[4][2], bHf2[4][2], bLf2[4][2];
                ldB32(bHf,  vbH, 0,  k0, lane);
                ldB32(bHf2, vbH, 32, k0, lane);
                ldB32(bLf,  vbL, 0,  k0, lane);
                ldB32(bLf2, vbL, 32, k0, lane);
                uint32_t a0 = ph01[gp], a1 = ph23[gp], a2 = ph01[gp+1], a3 = ph23[gp+1];
                uint32_t e0 = pl01[gp], e1 = pl23[gp], e2 = pl01[gp+1], e3 = pl23[gp+1];
                #pragma unroll
                for (int f = 0; f < 4; f++) {
                    mma16816(O1[f],   a0, a1, a2, a3, bHf[f][0],  bHf[f][1]);
                    mma16816(O1[f+4], a0, a1, a2, a3, bHf2[f][0], bHf2[f][1]);
                }
                #pragma unroll
                for (int f = 0; f < 4; f++) {
                    mma16816(O1[f],   a0, a1, a2, a3, bLf[f][0],  bLf[f][1]);
                    mma16816(O1[f+4], a0, a1, a2, a3, bLf2[f][0], bLf2[f][1]);
                }
                #pragma unroll
                for (int f = 0; f < 4; f++) {
                    mma16816(O1[f],   e0, e1, e2, e3, bHf[f][0],  bHf[f][1]);
                    mma16816(O1[f+4], e0, e1, e2, e3, bHf2[f][0], bHf2[f][1]);
                }
            }
        }

        // ---- path 2: P2 = exp(l*cq*rr - m2), accumulate O2 += P2 @ CP ----
        {
            uint32_t ph01[8], ph23[8], pl01[8], pl23[8];
            float ps0 = 0.f, ps1 = 0.f;
            #pragma unroll
            for (int f = 0; f < 8; f++) {
                float p0 = __expf(S[f][0]*cqv[f][0]*rr0 - m2n0);
                float p1v = __expf(S[f][1]*cqv[f][1]*rr0 - m2n0);
                float p2v = __expf(S[f][2]*cqv[f][0]*rr1 - m2n1);
                float p3v = __expf(S[f][3]*cqv[f][1]*rr1 - m2n1);
                ps0 += p0 + p1v; ps1 += p2v + p3v;
                ph01[f] = packhi2(p0, p1v);  pl01[f] = packlo2(p0, p1v);
                ph23[f] = packhi2(p2v, p3v); pl23[f] = packlo2(p2v, p3v);
            }
            #pragma unroll
            for (int o = 1; o <= 2; o <<= 1) {
                ps0 += __shfl_xor_sync(0xffffffffu, ps0, o);
                ps1 += __shfl_xor_sync(0xffffffffu, ps1, o);
            }
            s2_0 = s2_0 * f20 + ps0; s2_1 = s2_1 * f21 + ps1;
            #pragma unroll
            for (int kk = 0; kk < 64; kk += 16) {
                int cch = kk >> 5, k0 = kk & 16;
                int gp = kk >> 3;
                uint32_t pbH = bb + 40960 + cch*5120, pbL = bb + 51200 + cch*5120;
                uint32_t bHf[4][2], bLf[4][2], bHf2[4][2], bLf2[4][2];
                ldB32(bHf,  pbH, 0,  k0, lane);
                ldB32(bHf2, pbH, 32, k0, lane);
                ldB32(bLf,  pbL, 0,  k0, lane);
                ldB32(bLf2, pbL, 32, k0, lane);
                uint32_t a0 = ph01[gp], a1 = ph23[gp], a2 = ph01[gp+1], a3 = ph23[gp+1];
                uint32_t e0 = pl01[gp], e1 = pl23[gp], e2 = pl01[gp+1], e3 = pl23[gp+1];
                #pragma unroll
                for (int f = 0; f < 4; f++) {
                    mma16816(O2[f],   a0, a1, a2, a3, bHf[f][0],  bHf[f][1]);
                    mma16816(O2[f+4], a0, a1, a2, a3, bHf2[f][0], bHf2[f][1]);
                }
                #pragma unroll
                for (int f = 0; f < 4; f++) {
                    mma16816(O2[f],   a0, a1, a2, a3, bLf[f][0],  bLf[f][1]);
                    mma16816(O2[f+4], a0, a1, a2, a3, bLf2[f][0], bLf2[f][1]);
                }
                #pragma unroll
                for (int f = 0; f < 4; f++) {
                    mma16816(O2[f],   e0, e1, e2, e3, bHf[f][0],  bHf[f][1]);
                    mma16816(O2[f+4], e0, e1, e2, e3, bHf2[f][0], bHf2[f][1]);
                }
            }
        }
        __syncthreads();
        buf ^= 1;
    }
    #undef FLOAD

    // ---- epilogue: values rows (tokens), stats for attn_fix ----
    int b_ = bh / HH, h_ = bh % HH;
    float is10 = 1.f/s1_0, is11 = 1.f/s1_1, is20 = 1.f/s2_0, is21 = 1.f/s2_1;
    size_t ob0 = (size_t)(b_*SS + 1 + gr0)*EE + h_*DH;
    size_t ob1 = (size_t)(b_*SS + 1 + gr1)*EE + h_*DH;
    #pragma unroll
    for (int f = 0; f < 8; f++) {
        int d = f*8 + tig*2;
        float v0 = O1[f][0]*is10 + O2[f][0]*is20;
        float v1 = O1[f][1]*is10 + O2[f][1]*is20;
        float v2 = O1[f][2]*is11 + O2[f][2]*is21;
        float v3 = O1[f][3]*is11 + O2[f][3]*is21;
        *(uint32_t*)&VALSH[ob0 + d] = packhi2(v0, v1);
        *(uint32_t*)&VALSL[ob0 + d] = packlo2(v0, v1);
        *(uint32_t*)&VALSH[ob1 + d] = packhi2(v2, v3);
        *(uint32_t*)&VALSL[ob1 + d] = packlo2(v2, v3);
    }
    if (tig == 0) {
        M1g[(size_t)bh*SQ + gr0] = m1_0; S1g[(size_t)bh*SQ + gr0] = is10;
        M1g[(size_t)bh*SQ + gr1] = m1_1; S1g[(size_t)bh*SQ + gr1] = is11;
    }
}

// ============================================================
// attn_fix: attn = exp(l - M)/S in place. one row per block.
// ============================================================
__global__ void attn_fix(float* __restrict__ attn) {
    int row = blockIdx.x;
    float m = M1g[row], si = S1g[row];
    float4* p = (float4*)(attn + (size_t)row*SQ);
    float4 v = p[threadIdx.x];
    v.x = __expf(v.x - m)*si;
    v.y = __expf(v.y - m)*si;
    v.z = __expf(v.z - m)*si;
    v.w = __expf(v.w - m)*si;
    p[threadIdx.x] = v;
}

// ============================================================
// out: VALS @ Wo^T + bo. grid(8,33), M guard at 4100
// ============================================================
__global__ void __launch_bounds__(256) out_mm(const float* __restrict__ bo,
                                             float* __restrict__ out)
{
    extern __shared__ uint8_t dyn[];
    uint32_t sb = s2u(dyn);
    int tid = threadIdx.x, wid = tid >> 5, lane = tid & 31;
    int m0 = blockIdx.y * 128, n0 = blockIdx.x * 128;

    const bf16* aH = VALSH + (size_t)m0*EE;
    const bf16* aL = VALSL + (size_t)m0*EE;
    const bf16* bH = WoH + (size_t)n0*EE;
    const bf16* bL = WoL + (size_t)n0*EE;

    float acc[4][4][4] = {};
    int wm = wid & 1, wn = wid >> 1;
    int mrow0 = wm*64, ncol0 = wn*32;

    ld_tile32(sb,         aH, EE, 128);
    ld_tile32(sb + 10240, aL, EE, 128);
    ld_tile32(sb + 20480, bH, EE, 128);
    ld_tile32(sb + 30720, bL, EE, 128);
    CPA_COMMIT();
    int buf = 0;
    for (int ch = 0; ch < 32; ch++) {
        if (ch + 1 < 32) {
            uint32_t nb = sb + (buf^1)*40960;
            int kt = (ch + 1) * 32;
            ld_tile32(nb,         aH + kt, EE, 128);
            ld_tile32(nb + 10240, aL + kt, EE, 128);
            ld_tile32(nb + 20480, bH + kt, EE, 128);
            ld_tile32(nb + 30720, bL + kt, EE, 128);
            CPA_COMMIT();
            CPA_WAIT1();
        } else CPA_WAIT0();
        __syncthreads();
        uint32_t base = sb + buf*40960;
        wmma_step<4>(acc, base, base+10240, base+20480, base+30720, mrow0, ncol0, 0,  lane);
        wmma_step<4>(acc, base, base+10240, base+20480, base+30720, mrow0, ncol0, 16, lane);
        __syncthreads();
        buf ^= 1;
    }

    int rbase = mrow0 + (lane >> 2);
    int cbase = ncol0 + (lane & 3)*2;
    #pragma unroll
    for (int mi = 0; mi < 4; mi++)
        #pragma unroll
        for (int half = 0; half < 2; half++) {
            int mr = m0 + rbase + mi*16 + half*8;
            if (mr >= MROWS_OUT) continue;
            #pragma unroll
            for (int nj = 0; nj < 4; nj++) {
                int col = n0 + cbase + nj*8;
                *(float2*)&out[(size_t)mr*EE + col] =
                    make_float2(acc[mi][nj][half*2] + bo[col],
                                acc[mi][nj][half*2+1] + bo[col+1]);
            }
        }
}

// ============================================================
// cls token projection + CN2. grid BH, block 64
// ============================================================
__global__ void clsproj_kernel(const float* __restrict__ x,
                               const float* __restrict__ Wq,
                               const float* __restrict__ bq) {
    int bh = blockIdx.x;
    int b_ = bh / HH, h_ = bh % HH;
    int d  = threadIdx.x;
    int j  = h_*DH + d;
    const float* xr = x  + (size_t)(b_*SS)*EE;
    const float* wr = Wq + (size_t)j*EE;
    float s = 0.f;
    for (int e = 0; e < EE; e += 4) {
        float4 xv = *(const float4*)(xr + e);
        float4 wv = *(const float4*)(wr + e);
        s += xv.x*wv.x + xv.y*wv.y + xv.z*wv.z + xv.w*wv.w;
    }
    s += bq[j];
    CVEC[bh*DH + d] = s;
    __shared__ float red[64];
    red[d] = s*s; __syncthreads();
    for (int o = 32; o > 0; o >>= 1) { if (d < o) red[d] += red[d+o]; __syncthreads(); }
    if (d == 0) CN2[bh] = fmaxf(red[0], EPSF);
}

// ============================================================
// per-row q stats: QN2 and CQ. grid BH*SQ/8, block 256
// ============================================================
__global__ void qstats_kernel() {
    int row  = blockIdx.x*8 + (threadIdx.x >> 5);
    int lane = threadIdx.x & 31;
    int bh   = row >> 10;
    const float* qr = QS   + (size_t)row*DH;
    const float* cv = CVEC + bh*DH;
    float n2 = 0.f, cq = 0.f;
    #pragma unroll
    for (int d = lane; d < DH; d += 32) {
        float qv = qr[d];
        n2 += qv*qv;
        cq += qv*cv[d];
    }
    #pragma unroll
    for (int o = 16; o > 0; o >>= 1) {
        n2 += __shfl_xor_sync(0xffffffffu, n2, o);
        cq += __shfl_xor_sync(0xffffffffu, cq, o);
    }
    if (lane == 0) { QN2[row] = fmaxf(n2, EPSF); CQg[row] = cq; }
}

// ============================================================
// cls path: ck softmax -> cls_out row (hi/lo into VALS). grid BH, block 256
// ============================================================
__global__ void cls_kernel() {
    int bh = blockIdx.x;
    int tid = threadIdx.x;
    const float* Kp = KS + (size_t)bh*SQ*DH;
    const float* Vp = VS + (size_t)bh*SQ*DH;
    __shared__ float p_s[SQ];
    __shared__ float red[256];
    __shared__ float c_s[DH];
    if (tid < DH) c_s[tid] = CVEC[bh*DH + tid];
    __syncthreads();

    float scale = rsqrtf(64.0f * CN2[bh]);
    float lo[4];
    #pragma unroll
    for (int p = 0; p < 4; p++) {
        int j = tid + p*256;
        const float* kr = Kp + (size_t)j*DH;
        float s = 0.f;
        #pragma unroll
        for (int d = 0; d < DH; d += 4) {
            float4 kv = *(const float4*)(kr + d);
            s += c_s[d]*kv.x + c_s[d+1]*kv.y + c_s[d+2]*kv.z + c_s[d+3]*kv.w;
        }
        lo[p] = s * scale;
    }
    float m = fmaxf(fmaxf(lo[0],lo[1]), fmaxf(lo[2],lo[3]));
    red[tid] = m; __syncthreads();
    #pragma unroll
    for (int o = 128; o > 0; o >>= 1) { if (tid < o) red[tid] = fmaxf(red[tid], red[tid+o]); __syncthreads(); }
    m = red[0]; __syncthreads();
    float e[4], s = 0.f;
    #pragma unroll
    for (int p = 0; p < 4; p++) { e[p] = __expf(lo[p] - m); s += e[p]; }
    red[tid] = s; __syncthreads();
    #pragma unroll
    for (int o = 128; o > 0; o >>= 1) { if (tid < o) red[tid] += red[tid+o]; __syncthreads(); }
    float inv = 1.0f / red[0]; __syncthreads();
    #pragma unroll
    for (int p = 0; p < 4; p++) p_s[tid + p*256] = e[p]*inv;
    __syncthreads();

    int d = tid & 63, g = tid >> 6;
    float acc = 0.f;
    for (int j = g*256; j < (g+1)*256; j++) acc += p_s[j] * Vp[(size_t)j*DH + d];
    red[tid] = acc; __syncthreads();
    if (g == 0) {
        float rsum = red[tid] + red[tid+64] + red[tid+128] + red[tid+192];
        int b_ = bh / HH, h_ = bh % HH;
        bf16 hi, lov; split2(rsum, hi, lov);
        size_t idx = (size_t)(b_*SS)*EE + h_*DH + d;
        VALSH[idx] = hi;
        VALSL[idx] = lov;
    }
}

extern "C" void kernel_launch(void* const* d_in, const int* in_sizes, int n_in,
                              void* d_out, int out_size) {
    const float* x  = (const float*)d_in[0];
    const float* Wq = (const float*)d_in[1];
    const float* bq = (const float*)d_in[2];
    const float* Wk = (const float*)d_in[3];
    const float* bk = (const float*)d_in[4];
    const float* Wv = (const float*)d_in[5];
    const float* bv = (const float*)d_in[6];
    const float* Wo = (const float*)d_in[7];
    const float* bo = (const float*)d_in[8];
    const float* Wc = (const float*)d_in[9];
    const float* bc = (const float*)d_in[10];

    float* out  = (float*)d_out;
    float* attn = out + (size_t)BB*SS*EE;

    cudaFuncSetAttribute(proj_mm,    cudaFuncAttributeMaxDynamicSharedMemorySize, 81920);
    cudaFuncSetAttribute(out_mm,     cudaFuncAttributeMaxDynamicSharedMemorySize, 81920);
    cudaFuncSetAttribute(fused_attn, cudaFuncAttributeMaxDynamicSharedMemorySize, 163840);

    bf16 *xh, *xl, *wqh, *wql, *wkh, *wkl, *wvh, *wvl, *wch, *wcl, *woh, *wol;
    cudaGetSymbolAddress((void**)&xh, XH);   cudaGetSymbolAddress((void**)&xl, XL);
    cudaGetSymbolAddress((void**)&wqh, WqH); cudaGetSymbolAddress((void**)&wql, WqL);
    cudaGetSymbolAddress((void**)&wkh, WkH); cudaGetSymbolAddress((void**)&wkl, WkL);
    cudaGetSymbolAddress((void**)&wvh, WvH); cudaGetSymbolAddress((void**)&wvl, WvL);
    cudaGetSymbolAddress((void**)&wch, WcH); cudaGetSymbolAddress((void**)&wcl, WcL);
    cudaGetSymbolAddress((void**)&woh, WoH); cudaGetSymbolAddress((void**)&wol, WoL);

    int nx4 = BB*SS*EE/4, nw4 = EE*EE/4;
    // 1: x conversion
    conv_kernel<<<(nx4+255)/256, 256>>>(x,  xh,  xl,  nx4);
    // 2: Wq + Wk
    convW_kernel<<<dim3((nw4+255)/256, 2), 256>>>(Wq, wqh, wql, Wk, wkh, wkl, nw4);
    // 3: Wv + Wc
    convW_kernel<<<dim3((nw4+255)/256, 2), 256>>>(Wv, wvh, wvl, Wc, wch, wcl, nw4);
    // 4: proj (ncu's launch #6 target)
    proj_mm<<<dim3(8,32,4), 256, 81920>>>(bq, bk, bv, bc);
    // 5: Wo conversion
    conv_kernel<<<(nw4+255)/256, 256>>>(Wo, woh, wol, nw4);
    // 6-7: cls projection + q stats
    clsproj_kernel<<<BH, 64>>>(x, Wq, bq);
    qstats_kernel<<<BH*SQ/8, 256>>>();
    // 8: fused attention (raw logits + values)
    fused_attn<<<dim3(8,BH), 256, 163840>>>(attn);
    // 9: attn normalization in place
    attn_fix<<<BH*SQ, 256>>>(attn);
    // 10: cls output row
    cls_kernel<<<BH, 256>>>();
    // 11: output projection
    out_mm<<<dim3(8,33), 256, 81920>>>(bo, out);
}

// round 9
// speedup vs baseline: 1.3549x; 1.1008x over previous
#include <cuda_runtime.h>
#include <cuda_bf16.h>
#include <cuda_fp16.h>
#include <cstdint>

#define BB 4
#define SS 1025
#define SQ 1024
#define EE 1024
#define HH 16
#define DH 64
#define BH (BB*HH)
#define EPSF 1e-5f
#define MROWS_OUT (BB*SS)     // 4100
#define MTILES_OUT 33         // 33*128 = 4224

typedef __nv_bfloat16 bf16;

// ---------------- device scratch (allocation-free) ----------------
__device__ float QS[BH*SQ*DH];          // fp32 q  (qstats)
__device__ float KS[BH*SQ*DH];          // fp32 k  (cls path)
__device__ float VS[BH*SQ*DH];          // fp32 v  (cls path)
__device__ bf16 XH[BB*SS*EE],  XL[BB*SS*EE];
__device__ bf16 WqH[EE*EE], WqL[EE*EE], WkH[EE*EE], WkL[EE*EE];
__device__ bf16 WvH[EE*EE], WvL[EE*EE], WcH[EE*EE], WcL[EE*EE];
__device__ bf16 QH[BH*SQ*DH], QL[BH*SQ*DH], KH[BH*SQ*DH], KL[BH*SQ*DH];
// fp16 path (2-pass GEMMs). V/CP scaled x16, Wo scaled x64 (keeps lo-residuals normal).
__device__ __half VTHh[BH*DH*SQ], VTLh[BH*DH*SQ];      // (16*V)^T hi/lo
__device__ __half CPTHh[BH*DH*SQ], CPTLh[BH*DH*SQ];    // (16*CP)^T hi/lo
__device__ __half WoHh[EE*EE], WoLh[EE*EE];            // 64*Wo hi/lo
__device__ __half VALSh[(size_t)MTILES_OUT*128*EE];    // values, single fp16
__device__ float CVEC[BH*DH];
__device__ float CN2[BH];
__device__ float QN2[BH*SQ];
__device__ float CQg[BH*SQ];
__device__ float M1g[BH*SQ];            // final row max (path 1)
__device__ float S1g[BH*SQ];            // 1/rowsum (path 1)

// ---------------- warp-mma helpers ----------------
__device__ __forceinline__ uint32_t s2u(const void* p) {
    uint32_t a;
    asm("{ .reg .u64 t; cvta.to.shared.u64 t, %1; cvt.u32.u64 %0, t; }" : "=r"(a) : "l"(p));
    return a;
}
#define LDSM4(R0,R1,R2,R3,addr) \
    asm volatile("ldmatrix.sync.aligned.m8n8.x4.shared.b16 {%0,%1,%2,%3}, [%4];" \
        : "=r"(R0),"=r"(R1),"=r"(R2),"=r"(R3) : "r"(addr))

__device__ __forceinline__ void mma16816(float* c, uint32_t a0, uint32_t a1,
                                         uint32_t a2, uint32_t a3,
                                         uint32_t b0, uint32_t b1) {
    asm volatile(
        "mma.sync.aligned.m16n8k16.row.col.f32.bf16.bf16.f32 "
        "{%0,%1,%2,%3}, {%4,%5,%6,%7}, {%8,%9}, {%0,%1,%2,%3};"
        : "+f"(c[0]), "+f"(c[1]), "+f"(c[2]), "+f"(c[3])
        : "r"(a0), "r"(a1), "r"(a2), "r"(a3), "r"(b0), "r"(b1));
}
__device__ __forceinline__ void mma16816h(float* c, uint32_t a0, uint32_t a1,
                                          uint32_t a2, uint32_t a3,
                                          uint32_t b0, uint32_t b1) {
    asm volatile(
        "mma.sync.aligned.m16n8k16.row.col.f32.f16.f16.f32 "
        "{%0,%1,%2,%3}, {%4,%5,%6,%7}, {%8,%9}, {%0,%1,%2,%3};"
        : "+f"(c[0]), "+f"(c[1]), "+f"(c[2]), "+f"(c[3])
        : "r"(a0), "r"(a1), "r"(a2), "r"(a3), "r"(b0), "r"(b1));
}

// bf16 3-pass k16 step over MT*16 x 32 warp tile (pass-ordered)
template<int MT>
__device__ __forceinline__ void wmma_step(float (*acc)[4][4],
    uint32_t aHb, uint32_t aLb, uint32_t bHb, uint32_t bLb,
    int mrow0, int ncol0, int k0, int lane)
{
    uint32_t aH[MT][4], aL[MT][4];
    #pragma unroll
    for (int mi = 0; mi < MT; mi++) {
        uint32_t off = ((uint32_t)(mrow0 + mi*16 + (lane & 15))*40u + (uint32_t)k0 + ((lane >> 4) << 3)) * 2u;
        LDSM4(aH[mi][0], aH[mi][1], aH[mi][2], aH[mi][3], aHb + off);
        LDSM4(aL[mi][0], aL[mi][1], aL[mi][2], aL[mi][3], aLb + off);
    }
    uint32_t bHf[4][2], bLf[4][2];
    int j = lane >> 3;
    #pragma unroll
    for (int p = 0; p < 2; p++) {
        uint32_t off = ((uint32_t)(ncol0 + p*16 + ((j >> 1) << 3) + (lane & 7))*40u + (uint32_t)k0 + ((j & 1) << 3)) * 2u;
        uint32_t r0, r1, r2, r3;
        LDSM4(r0, r1, r2, r3, bHb + off);
        bHf[p*2][0] = r0; bHf[p*2][1] = r1; bHf[p*2+1][0] = r2; bHf[p*2+1][1] = r3;
        LDSM4(r0, r1, r2, r3, bLb + off);
        bLf[p*2][0] = r0; bLf[p*2][1] = r1; bLf[p*2+1][0] = r2; bLf[p*2+1][1] = r3;
    }
    #pragma unroll
    for (int mi = 0; mi < MT; mi++)
        #pragma unroll
        for (int nj = 0; nj < 4; nj++)
            mma16816(acc[mi][nj], aH[mi][0], aH[mi][1], aH[mi][2], aH[mi][3], bHf[nj][0], bHf[nj][1]);
    #pragma unroll
    for (int mi = 0; mi < MT; mi++)
        #pragma unroll
        for (int nj = 0; nj < 4; nj++)
            mma16816(acc[mi][nj], aH[mi][0], aH[mi][1], aH[mi][2], aH[mi][3], bLf[nj][0], bLf[nj][1]);
    #pragma unroll
    for (int mi = 0; mi < MT; mi++)
        #pragma unroll
        for (int nj = 0; nj < 4; nj++)
            mma16816(acc[mi][nj], aL[mi][0], aL[mi][1], aL[mi][2], aL[mi][3], bHf[nj][0], bHf[nj][1]);
}

// fp16 2-pass k16 step: A single (aB), B hi/lo. MT*16 x 32 warp tile.
template<int MT>
__device__ __forceinline__ void wmma_step2h(float (*acc)[4][4],
    uint32_t aB, uint32_t bHb, uint32_t bLb,
    int mrow0, int ncol0, int k0, int lane)
{
    uint32_t aF[MT][4];
    #pragma unroll
    for (int mi = 0; mi < MT; mi++) {
        uint32_t off = ((uint32_t)(mrow0 + mi*16 + (lane & 15))*40u + (uint32_t)k0 + ((lane >> 4) << 3)) * 2u;
        LDSM4(aF[mi][0], aF[mi][1], aF[mi][2], aF[mi][3], aB + off);
    }
    uint32_t bHf[4][2], bLf[4][2];
    int j = lane >> 3;
    #pragma unroll
    for (int p = 0; p < 2; p++) {
        uint32_t off = ((uint32_t)(ncol0 + p*16 + ((j >> 1) << 3) + (lane & 7))*40u + (uint32_t)k0 + ((j & 1) << 3)) * 2u;
        uint32_t r0, r1, r2, r3;
        LDSM4(r0, r1, r2, r3, bHb + off);
        bHf[p*2][0] = r0; bHf[p*2][1] = r1; bHf[p*2+1][0] = r2; bHf[p*2+1][1] = r3;
        LDSM4(r0, r1, r2, r3, bLb + off);
        bLf[p*2][0] = r0; bLf[p*2][1] = r1; bLf[p*2+1][0] = r2; bLf[p*2+1][1] = r3;
    }
    #pragma unroll
    for (int mi = 0; mi < MT; mi++)
        #pragma unroll
        for (int nj = 0; nj < 4; nj++)
            mma16816h(acc[mi][nj], aF[mi][0], aF[mi][1], aF[mi][2], aF[mi][3], bHf[nj][0], bHf[nj][1]);
    #pragma unroll
    for (int mi = 0; mi < MT; mi++)
        #pragma unroll
        for (int nj = 0; nj < 4; nj++)
            mma16816h(acc[mi][nj], aF[mi][0], aF[mi][1], aF[mi][2], aF[mi][3], bLf[nj][0], bLf[nj][1]);
}

// 4 n8-frags (32 cols) from smem tile (stride 40)
__device__ __forceinline__ void ldB32(uint32_t (*bf)[2], uint32_t base, int n0_, int k0, int lane) {
    int j = lane >> 3;
    #pragma unroll
    for (int p = 0; p < 2; p++) {
        uint32_t off = ((uint32_t)(n0_ + p*16 + ((j >> 1) << 3) + (lane & 7))*40u + (uint32_t)k0 + ((j & 1) << 3)) * 2u;
        uint32_t r0, r1, r2, r3;
        LDSM4(r0, r1, r2, r3, base + off);
        bf[p*2][0] = r0; bf[p*2][1] = r1; bf[p*2+1][0] = r2; bf[p*2+1][1] = r3;
    }
}

// load nrows x 32 b16 elems into smem tile (stride 40 elems) via cp.async
__device__ __forceinline__ void ld_tile32(uint32_t sdst, const void* gv, size_t rstride, int nrows) {
    const bf16* g = (const bf16*)gv;
    int tid = threadIdx.x;
    int tot = nrows * 4;
    for (int u = tid; u < tot; u += 256) {
        int r = u >> 2, c = u & 3;
        uint32_t dst = sdst + (uint32_t)(r*80 + c*16);
        const bf16* src = g + (size_t)r * rstride + (c << 3);
        asm volatile("cp.async.cg.shared.global [%0], [%1], 16;" :: "r"(dst), "l"(src) : "memory");
    }
}
#define CPA_COMMIT() asm volatile("cp.async.commit_group;" ::: "memory")
#define CPA_WAIT1()  asm volatile("cp.async.wait_group 1;" ::: "memory")
#define CPA_WAIT0()  asm volatile("cp.async.wait_group 0;" ::: "memory")

__device__ __forceinline__ void split2(float v, bf16& h, bf16& l) {
    h = __float2bfloat16(v);
    l = __float2bfloat16(v - __bfloat162float(h));
}
__device__ __forceinline__ void split2h(float v, __half& h, __half& l) {
    h = __float2half(v);
    l = __float2half(v - __half2float(h));
}
__device__ __forceinline__ uint32_t pack2(bf16 a, bf16 b) {
    return (uint32_t)__bfloat16_as_ushort(a) | ((uint32_t)__bfloat16_as_ushort(b) << 16);
}
__device__ __forceinline__ uint32_t packh2(float a, float b) {
    __half2 t = __floats2half2_rn(a, b);
    return *(uint32_t*)&t;
}
__device__ __forceinline__ uint32_t packh2x(__half a, __half b) {
    return (uint32_t)__half_as_ushort(a) | ((uint32_t)__half_as_ushort(b) << 16);
}

// ============================================================
// fp32 -> bf16 hi/lo split conversion. n4 = n/4
// ============================================================
__device__ __forceinline__ void conv_body(const float* __restrict__ s,
                                          bf16* __restrict__ h,
                                          bf16* __restrict__ l, int i) {
    float4 v = ((const float4*)s)[i];
    bf16 h0, h1, h2, h3, l0, l1, l2, l3;
    split2(v.x, h0, l0); split2(v.y, h1, l1); split2(v.z, h2, l2); split2(v.w, h3, l3);
    uint2 hp, lp;
    hp.x = pack2(h0, h1); hp.y = pack2(h2, h3);
    lp.x = pack2(l0, l1); lp.y = pack2(l2, l3);
    ((uint2*)h)[i] = hp;
    ((uint2*)l)[i] = lp;
}
__global__ void conv_kernel(const float* __restrict__ s, bf16* __restrict__ h,
                            bf16* __restrict__ l, int n4) {
    int i = blockIdx.x * 256 + threadIdx.x;
    if (i >= n4) return;
    conv_body(s, h, l, i);
}
__global__ void convW_kernel(const float* __restrict__ s0, bf16* __restrict__ h0,
                             bf16* __restrict__ l0,
                             const float* __restrict__ s1, bf16* __restrict__ h1,
                             bf16* __restrict__ l1, int n4) {
    int i = blockIdx.x * 256 + threadIdx.x;
    if (i >= n4) return;
    if (blockIdx.y == 0) conv_body(s0, h0, l0, i);
    else                 conv_body(s1, h1, l1, i);
}
// Wo: fp32 -> fp16 hi/lo of 64*w
__global__ void convWo_kernel(const float* __restrict__ s, __half* __restrict__ h,
                              __half* __restrict__ l, int n4) {
    int i = blockIdx.x * 256 + threadIdx.x;
    if (i >= n4) return;
    float4 v = ((const float4*)s)[i];
    __half h0, h1, h2, h3, l0, l1, l2, l3;
    split2h(v.x*64.f, h0, l0); split2h(v.y*64.f, h1, l1);
    split2h(v.z*64.f, h2, l2); split2h(v.w*64.f, h3, l3);
    uint2 hp, lp;
    hp.x = packh2x(h0, h1); hp.y = packh2x(h2, h3);
    lp.x = packh2x(l0, l1); lp.y = packh2x(l2, l3);
    ((uint2*)h)[i] = hp;
    ((uint2*)l)[i] = lp;
}

// ============================================================
// proj: 128x128 tile of (xt @ W^T + b) via warp mma. grid(8,32,4) block 256
// ============================================================
__global__ void __launch_bounds__(256) proj_mm(
    const float* __restrict__ b0, const float* __restrict__ b1,
    const float* __restrict__ b2, const float* __restrict__ b3)
{
    extern __shared__ uint8_t dyn[];
    uint32_t sb = s2u(dyn);
    int tid = threadIdx.x, wid = tid >> 5, lane = tid & 31;

    int w = blockIdx.z;
    const bf16* WHp = (w==0)?WqH:(w==1)?WkH:(w==2)?WvH:WcH;
    const bf16* WLp = (w==0)?WqL:(w==1)?WkL:(w==2)?WvL:WcL;
    const float* bias = (w==0)?b0:(w==1)?b1:(w==2)?b2:b3;

    int m0 = blockIdx.y * 128, n0 = blockIdx.x * 128;
    int b_ = m0 >> 10, i0 = m0 & 1023;

    const bf16* aH = XH + (size_t)(b_*SS + i0 + 1)*EE;
    const bf16* aL = XL + (size_t)(b_*SS + i0 + 1)*EE;
    const bf16* bH = WHp + (size_t)n0*EE;
    const bf16* bL = WLp + (size_t)n0*EE;

    float acc[4][4][4] = {};
    int wm = wid & 1, wn = wid >> 1;
    int mrow0 = wm*64, ncol0 = wn*32;

    ld_tile32(sb,         aH, EE, 128);
    ld_tile32(sb + 10240, aL, EE, 128);
    ld_tile32(sb + 20480, bH, EE, 128);
    ld_tile32(sb + 30720, bL, EE, 128);
    CPA_COMMIT();
    int buf = 0;
    for (int ch = 0; ch < 32; ch++) {
        if (ch + 1 < 32) {
            uint32_t nb = sb + (buf^1)*40960;
            int kt = (ch + 1) * 32;
            ld_tile32(nb,         aH + kt, EE, 128);
            ld_tile32(nb + 10240, aL + kt, EE, 128);
            ld_tile32(nb + 20480, bH + kt, EE, 128);
            ld_tile32(nb + 30720, bL + kt, EE, 128);
            CPA_COMMIT();
            CPA_WAIT1();
        } else CPA_WAIT0();
        __syncthreads();
        uint32_t base = sb + buf*40960;
        wmma_step<4>(acc, base, base+10240, base+20480, base+30720, mrow0, ncol0, 0,  lane);
        wmma_step<4>(acc, base, base+10240, base+20480, base+30720, mrow0, ncol0, 16, lane);
        __syncthreads();
        buf ^= 1;
    }

    int rbase = mrow0 + (lane >> 2);
    int cbase = ncol0 + (lane & 3)*2;
    #pragma unroll
    for (int mi = 0; mi < 4; mi++)
        #pragma unroll
        for (int half = 0; half < 2; half++) {
            int i = i0 + rbase + mi*16 + half*8;
            #pragma unroll
            for (int nj = 0; nj < 4; nj++) {
                int col = n0 + cbase + nj*8;
                int h2 = col >> 6, d2 = col & 63;
                float v0 = acc[mi][nj][half*2]   + bias[col];
                float v1 = acc[mi][nj][half*2+1] + bias[col+1];
                size_t qi = ((size_t)(b_*HH + h2)*SQ + i)*DH + d2;
                size_t ti = ((size_t)(b_*HH + h2)*DH + d2)*SQ + i;
                if (w == 0) {
                    bf16 h0v, l0v, h1v, l1v;
                    split2(v0, h0v, l0v); split2(v1, h1v, l1v);
                    *(float2*)&QS[qi] = make_float2(v0, v1);
                    *(uint32_t*)&QH[qi] = pack2(h0v, h1v);
                    *(uint32_t*)&QL[qi] = pack2(l0v, l1v);
                } else if (w == 1) {
                    bf16 h0v, l0v, h1v, l1v;
                    split2(v0, h0v, l0v); split2(v1, h1v, l1v);
                    *(float2*)&KS[qi] = make_float2(v0, v1);
                    *(uint32_t*)&KH[qi] = pack2(h0v, h1v);
                    *(uint32_t*)&KL[qi] = pack2(l0v, l1v);
                } else if (w == 2) {
                    *(float2*)&VS[qi] = make_float2(v0, v1);
                    __half h0v, l0v, h1v, l1v;
                    split2h(v0*16.f, h0v, l0v); split2h(v1*16.f, h1v, l1v);
                    VTHh[ti] = h0v;      VTLh[ti] = l0v;
                    VTHh[ti + SQ] = h1v; VTLh[ti + SQ] = l1v;
                } else {
                    __half h0v, l0v, h1v, l1v;
                    split2h(v0*16.f, h0v, l0v); split2h(v1*16.f, h1v, l1v);
                    CPTHh[ti] = h0v;      CPTLh[ti] = l0v;
                    CPTHh[ti + SQ] = h1v; CPTLh[ti + SQ] = l1v;
                }
            }
        }
}

// ============================================================
// fused attention: S=QK^T (bf16 3-pass) -> raw l to attn, dual online softmax,
// O1 += P1@V, O2 += P2@CP (fp16 2-pass, V/CP scaled x16). grid(8, 64) block 256
// ============================================================
__global__ void __launch_bounds__(256) fused_attn(float* __restrict__ attn)
{
    extern __shared__ uint8_t dyn[];
    uint32_t sQ = s2u(dyn);
    uint32_t sT = sQ + 40960;            // two 61440 buffers
    int tid = threadIdx.x, wid = tid >> 5, lane = tid & 31;
    int bh = blockIdx.y;
    int m0 = blockIdx.x * 128;
    int mrow0 = wid * 16;
    int g = lane >> 2, tig = lane & 3;
    int r0 = mrow0 + g, r1 = r0 + 8;
    int gr0 = m0 + r0, gr1 = m0 + r1;

    float qn0 = QN2[(size_t)bh*SQ + gr0], qn1 = QN2[(size_t)bh*SQ + gr1];
    float cn = CN2[bh];
    float sc0 = rsqrtf(64.0f * qn0), sc1r = rsqrtf(64.0f * qn1);
    float rr0 = rsqrtf(qn0 * cn), rr1 = rsqrtf(qn1 * cn);

    float* attnb = attn + (size_t)bh*SQ*SQ;
    const float* cqrow = CQg + (size_t)bh*SQ;

    {
        const bf16* qh = QH + (size_t)bh*SQ*DH + (size_t)m0*DH;
        const bf16* ql = QL + (size_t)bh*SQ*DH + (size_t)m0*DH;
        ld_tile32(sQ,         qh,      DH, 128);
        ld_tile32(sQ + 10240, qh + 32, DH, 128);
        ld_tile32(sQ + 20480, ql,      DH, 128);
        ld_tile32(sQ + 30720, ql + 32, DH, 128);
        CPA_COMMIT();
    }

    #define FLOAD(bb, jt) do { \
        int j0_ = (jt) * 64; \
        const bf16* kh_ = KH + (size_t)bh*SQ*DH + (size_t)j0_*DH; \
        const bf16* kl_ = KL + (size_t)bh*SQ*DH + (size_t)j0_*DH; \
        const __half* vh_ = VTHh + (size_t)bh*DH*SQ + j0_; \
        const __half* vl_ = VTLh + (size_t)bh*DH*SQ + j0_; \
        const __half* ph_ = CPTHh + (size_t)bh*DH*SQ + j0_; \
        const __half* pl_ = CPTLh + (size_t)bh*DH*SQ + j0_; \
        ld_tile32((bb),        kh_,      DH, 64); \
        ld_tile32((bb)+5120,   kh_ + 32, DH, 64); \
        ld_tile32((bb)+10240,  kl_,      DH, 64); \
        ld_tile32((bb)+15360,  kl_ + 32, DH, 64); \
        ld_tile32((bb)+20480,  vh_,      SQ, 64); \
        ld_tile32((bb)+25600,  vh_ + 32, SQ, 64); \
        ld_tile32((bb)+30720,  vl_,      SQ, 64); \
        ld_tile32((bb)+35840,  vl_ + 32, SQ, 64); \
        ld_tile32((bb)+40960,  ph_,      SQ, 64); \
        ld_tile32((bb)+46080,  ph_ + 32, SQ, 64); \
        ld_tile32((bb)+51200,  pl_,      SQ, 64); \
        ld_tile32((bb)+56320,  pl_ + 32, SQ, 64); \
        CPA_COMMIT(); \
    } while (0)

    float O1[8][4] = {}, O2[8][4] = {};
    float m1_0 = -1e30f, m1_1 = -1e30f, m2_0 = -1e30f, m2_1 = -1e30f;
    float s1_0 = 0.f, s1_1 = 0.f, s2_0 = 0.f, s2_1 = 0.f;

    FLOAD(sT, 0);
    int buf = 0;
    for (int jt = 0; jt < 16; jt++) {
        if (jt + 1 < 16) { FLOAD(sT + (buf^1)*61440, jt + 1); CPA_WAIT1(); }
        else CPA_WAIT0();
        __syncthreads();
        uint32_t bb = sT + buf*61440;
        int j0 = jt * 64;

        // ---- S = Q K^T (bf16 3-pass, pass-ordered) ----
        float S[8][4] = {};
        #pragma unroll
        for (int kk = 0; kk < 64; kk += 16) {
            int cch = kk >> 5, k0 = kk & 16;
            uint32_t aQH = sQ + cch*10240;
            uint32_t aQL = sQ + 20480 + cch*10240;
            uint32_t a0, a1, a2, a3, e0, e1, e2, e3;
            uint32_t offA = ((uint32_t)(mrow0 + (lane & 15))*40u + (uint32_t)k0 + ((lane >> 4) << 3)) * 2u;
            LDSM4(a0, a1, a2, a3, aQH + offA);
            LDSM4(e0, e1, e2, e3, aQL + offA);
            uint32_t bHf[4][2], bLf[4][2], bHf2[4][2], bLf2[4][2];
            uint32_t kbH = bb + cch*5120, kbL = bb + 10240 + cch*5120;
            ldB32(bHf,  kbH, 0,  k0, lane);
            ldB32(bHf2, kbH, 32, k0, lane);
            ldB32(bLf,  kbL, 0,  k0, lane);
            ldB32(bLf2, kbL, 32, k0, lane);
            #pragma unroll
            for (int f = 0; f < 4; f++) {
                mma16816(S[f],   a0, a1, a2, a3, bHf[f][0],  bHf[f][1]);
                mma16816(S[f+4], a0, a1, a2, a3, bHf2[f][0], bHf2[f][1]);
            }
            #pragma unroll
            for (int f = 0; f < 4; f++) {
                mma16816(S[f],   a0, a1, a2, a3, bLf[f][0],  bLf[f][1]);
                mma16816(S[f+4], a0, a1, a2, a3, bLf2[f][0], bLf2[f][1]);
            }
            #pragma unroll
            for (int f = 0; f < 4; f++) {
                mma16816(S[f],   e0, e1, e2, e3, bHf[f][0],  bHf[f][1]);
                mma16816(S[f+4], e0, e1, e2, e3, bHf2[f][0], bHf2[f][1]);
            }
        }

        // ---- scale to l, store raw, track maxes ----
        float cqv[8][2];
        float lmax0 = -1e30f, lmax1 = -1e30f, l2max0 = -1e30f, l2max1 = -1e30f;
        #pragma unroll
        for (int f = 0; f < 8; f++) {
            int col = j0 + f*8 + tig*2;
            float2 cq = *(const float2*)&cqrow[col];
            cqv[f][0] = cq.x; cqv[f][1] = cq.y;
            S[f][0] *= sc0;  S[f][1] *= sc0;
            S[f][2] *= sc1r; S[f][3] *= sc1r;
            *(float2*)&attnb[(size_t)gr0*SQ + col] = make_float2(S[f][0], S[f][1]);
            *(float2*)&attnb[(size_t)gr1*SQ + col] = make_float2(S[f][2], S[f][3]);
            lmax0 = fmaxf(lmax0, fmaxf(S[f][0], S[f][1]));
            lmax1 = fmaxf(lmax1, fmaxf(S[f][2], S[f][3]));
            l2max0 = fmaxf(l2max0, fmaxf(S[f][0]*cq.x*rr0, S[f][1]*cq.y*rr0));
            l2max1 = fmaxf(l2max1, fmaxf(S[f][2]*cq.x*rr1, S[f][3]*cq.y*rr1));
        }
        #pragma unroll
        for (int o = 1; o <= 2; o <<= 1) {
            lmax0  = fmaxf(lmax0,  __shfl_xor_sync(0xffffffffu, lmax0,  o));
            lmax1  = fmaxf(lmax1,  __shfl_xor_sync(0xffffffffu, lmax1,  o));
            l2max0 = fmaxf(l2max0, __shfl_xor_sync(0xffffffffu, l2max0, o));
            l2max1 = fmaxf(l2max1, __shfl_xor_sync(0xffffffffu, l2max1, o));
        }
        float m1n0 = fmaxf(m1_0, lmax0),  m1n1 = fmaxf(m1_1, lmax1);
        float m2n0 = fmaxf(m2_0, l2max0), m2n1 = fmaxf(m2_1, l2max1);
        float f10 = __expf(m1_0 - m1n0), f11 = __expf(m1_1 - m1n1);
        float f20 = __expf(m2_0 - m2n0), f21 = __expf(m2_1 - m2n1);
        m1_0 = m1n0; m1_1 = m1n1; m2_0 = m2n0; m2_1 = m2n1;
        #pragma unroll
        for (int f = 0; f < 8; f++) {
            O1[f][0] *= f10; O1[f][1] *= f10; O1[f][2] *= f11; O1[f][3] *= f11;
            O2[f][0] *= f20; O2[f][1] *= f20; O2[f][2] *= f21; O2[f][3] *= f21;
        }

        // ---- path 1: P1 = exp(l - m1) fp16, O1 += P1 @ (16V) 2-pass ----
        {
            uint32_t ph01[8], ph23[8];
            float ps0 = 0.f, ps1 = 0.f;
            #pragma unroll
            for (int f = 0; f < 8; f++) {
                float p0 = __expf(S[f][0] - m1n0), p1v = __expf(S[f][1] - m1n0);
                float p2v = __expf(S[f][2] - m1n1), p3v = __expf(S[f][3] - m1n1);
                ps0 += p0 + p1v; ps1 += p2v + p3v;
                ph01[f] = packh2(p0, p1v);
                ph23[f] = packh2(p2v, p3v);
            }
            #pragma unroll
            for (int o = 1; o <= 2; o <<= 1) {
                ps0 += __shfl_xor_sync(0xffffffffu, ps0, o);
                ps1 += __shfl_xor_sync(0xffffffffu, ps1, o);
            }
            s1_0 = s1_0 * f10 + ps0; s1_1 = s1_1 * f11 + ps1;
            #pragma unroll
            for (int kk = 0; kk < 64; kk += 16) {
                int cch = kk >> 5, k0 = kk & 16;
                int gp = kk >> 3;
                uint32_t vbH = bb + 20480 + cch*5120, vbL = bb + 30720 + cch*5120;
                uint32_t bHf[4][2], bLf[4][2], bHf2[4][2], bLf2[4][2];
                ldB32(bHf,  vbH, 0,  k0, lane);
                ldB32(bHf2, vbH, 32, k0, lane);
                ldB32(bLf,  vbL, 0,  k0, lane);
                ldB32(bLf2, vbL, 32, k0, lane);
                uint32_t a0 = ph01[gp], a1 = ph23[gp], a2 = ph01[gp+1], a3 = ph23[gp+1];
                #pragma unroll
                for (int f = 0; f < 4; f++) {
                    mma16816h(O1[f],   a0, a1, a2, a3, bHf[f][0],  bHf[f][1]);
                    mma16816h(O1[f+4], a0, a1, a2, a3, bHf2[f][0], bHf2[f][1]);
                }
                #pragma unroll
                for (int f = 0; f < 4; f++) {
                    mma16816h(O1[f],   a0, a1, a2, a3, bLf[f][0],  bLf[f][1]);
                    mma16816h(O1[f+4], a0, a1, a2, a3, bLf2[f][0], bLf2[f][1]);
                }
            }
        }

        // ---- path 2: P2 = exp(l*cq*rr - m2) fp16, O2 += P2 @ (16CP) 2-pass ----
        {
            uint32_t ph01[8], ph23[8];
            float ps0 = 0.f, ps1 = 0.f;
            #pragma unroll
            for (int f = 0; f < 8; f++) {
                float p0 = __expf(S[f][0]*cqv[f][0]*rr0 - m2n0);
                float p1v = __expf(S[f][1]*cqv[f][1]*rr0 - m2n0);
                float p2v = __expf(S[f][2]*cqv[f][0]*rr1 - m2n1);
                float p3v = __expf(S[f][3]*cqv[f][1]*rr1 - m2n1);
                ps0 += p0 + p1v; ps1 += p2v + p3v;
                ph01[f] = packh2(p0, p1v);
                ph23[f] = packh2(p2v, p3v);
            }
            #pragma unroll
            for (int o = 1; o <= 2; o <<= 1) {
                ps0 += __shfl_xor_sync(0xffffffffu, ps0, o);
                ps1 += __shfl_xor_sync(0xffffffffu, ps1, o);
            }
            s2_0 = s2_0 * f20 + ps0; s2_1 = s2_1 * f21 + ps1;
            #pragma unroll
            for (int kk = 0; kk < 64; kk += 16) {
                int cch = kk >> 5, k0 = kk & 16;
                int gp = kk >> 3;
                uint32_t pbH = bb + 40960 + cch*5120, pbL = bb + 51200 + cch*5120;
                uint32_t bHf[4][2], bLf[4][2], bHf2[4][2], bLf2[4][2];
                ldB32(bHf,  pbH, 0,  k0, lane);
                ldB32(bHf2, pbH, 32, k0, lane);
                ldB32(bLf,  pbL, 0,  k0, lane);
                ldB32(bLf2, pbL, 32, k0, lane);
                uint32_t a0 = ph01[gp], a1 = ph23[gp], a2 = ph01[gp+1], a3 = ph23[gp+1];
                #pragma unroll
                for (int f = 0; f < 4; f++) {
                    mma16816h(O2[f],   a0, a1, a2, a3, bHf[f][0],  bHf[f][1]);
                    mma16816h(O2[f+4], a0, a1, a2, a3, bHf2[f][0], bHf2[f][1]);
                }
                #pragma unroll
                for (int f = 0; f < 4; f++) {
                    mma16816h(O2[f],   a0, a1, a2, a3, bLf[f][0],  bLf[f][1]);
                    mma16816h(O2[f+4], a0, a1, a2, a3, bLf2[f][0], bLf2[f][1]);
                }
            }
        }
        __syncthreads();
        buf ^= 1;
    }
    #undef FLOAD

    // ---- epilogue (values rows; /16 undoes V/CP scale) ----
    int b_ = bh / HH, h_ = bh % HH;
    float is10 = 0.0625f/s1_0, is11 = 0.0625f/s1_1, is20 = 0.0625f/s2_0, is21 = 0.0625f/s2_1;
    size_t ob0 = (size_t)(b_*SS + 1 + gr0)*EE + h_*DH;
    size_t ob1 = (size_t)(b_*SS + 1 + gr1)*EE + h_*DH;
    #pragma unroll
    for (int f = 0; f < 8; f++) {
        int d = f*8 + tig*2;
        float v0 = O1[f][0]*is10 + O2[f][0]*is20;
        float v1 = O1[f][1]*is10 + O2[f][1]*is20;
        float v2 = O1[f][2]*is11 + O2[f][2]*is21;
        float v3 = O1[f][3]*is11 + O2[f][3]*is21;
        *(uint32_t*)&VALSh[ob0 + d] = packh2(v0, v1);
        *(uint32_t*)&VALSh[ob1 + d] = packh2(v2, v3);
    }
    if (tig == 0) {
        M1g[(size_t)bh*SQ + gr0] = m1_0; S1g[(size_t)bh*SQ + gr0] = s1_0 > 0.f ? 1.f/s1_0 : 0.f;
        M1g[(size_t)bh*SQ + gr1] = m1_1; S1g[(size_t)bh*SQ + gr1] = s1_1 > 0.f ? 1.f/s1_1 : 0.f;
    }
}

// ============================================================
// attn_fix: attn = exp(l - M)/S in place. one row per block.
// ============================================================
__global__ void attn_fix(float* __restrict__ attn) {
    int row = blockIdx.x;
    float m = M1g[row], si = S1g[row];
    float4* p = (float4*)(attn + (size_t)row*SQ);
    float4 v = p[threadIdx.x];
    v.x = __expf(v.x - m)*si;
    v.y = __expf(v.y - m)*si;
    v.z = __expf(v.z - m)*si;
    v.w = __expf(v.w - m)*si;
    p[threadIdx.x] = v;
}

// ============================================================
// out: VALS(f16) @ (64Wo)^T/64 + bo. fp16 2-pass. grid(8,33)
// smem: 2 x 3 tiles x 10240 = 61440
// ============================================================
__global__ void __launch_bounds__(256) out_mm(const float* __restrict__ bo,
                                             float* __restrict__ out)
{
    extern __shared__ uint8_t dyn[];
    uint32_t sb = s2u(dyn);
    int tid = threadIdx.x, wid = tid >> 5, lane = tid & 31;
    int m0 = blockIdx.y * 128, n0 = blockIdx.x * 128;

    const __half* aF = VALSh + (size_t)m0*EE;
    const __half* bH = WoHh + (size_t)n0*EE;
    const __half* bL = WoLh + (size_t)n0*EE;

    float acc[4][4][4] = {};
    int wm = wid & 1, wn = wid >> 1;
    int mrow0 = wm*64, ncol0 = wn*32;

    ld_tile32(sb,         aF, EE, 128);
    ld_tile32(sb + 10240, bH, EE, 128);
    ld_tile32(sb + 20480, bL, EE, 128);
    CPA_COMMIT();
    int buf = 0;
    for (int ch = 0; ch < 32; ch++) {
        if (ch + 1 < 32) {
            uint32_t nb = sb + (buf^1)*30720;
            int kt = (ch + 1) * 32;
            ld_tile32(nb,         aF + kt, EE, 128);
            ld_tile32(nb + 10240, bH + kt, EE, 128);
            ld_tile32(nb + 20480, bL + kt, EE, 128);
            CPA_COMMIT();
            CPA_WAIT1();
        } else CPA_WAIT0();
        __syncthreads();
        uint32_t base = sb + buf*30720;
        wmma_step2h<4>(acc, base, base+10240, base+20480, mrow0, ncol0, 0,  lane);
        wmma_step2h<4>(acc, base, base+10240, base+20480, mrow0, ncol0, 16, lane);
        __syncthreads();
        buf ^= 1;
    }

    int rbase = mrow0 + (lane >> 2);
    int cbase = ncol0 + (lane & 3)*2;
    const float inv64 = 1.0f/64.0f;
    #pragma unroll
    for (int mi = 0; mi < 4; mi++)
        #pragma unroll
        for (int half = 0; half < 2; half++) {
            int mr = m0 + rbase + mi*16 + half*8;
            if (mr >= MROWS_OUT) continue;
            #pragma unroll
            for (int nj = 0; nj < 4; nj++) {
                int col = n0 + cbase + nj*8;
                *(float2*)&out[(size_t)mr*EE + col] =
                    make_float2(acc[mi][nj][half*2]*inv64 + bo[col],
                                acc[mi][nj][half*2+1]*inv64 + bo[col+1]);
            }
        }
}

// ============================================================
// cls token projection + CN2. grid BH, block 64
// ============================================================
__global__ void clsproj_kernel(const float* __restrict__ x,
                               const float* __restrict__ Wq,
                               const float* __restrict__ bq) {
    int bh = blockIdx.x;
    int b_ = bh / HH, h_ = bh % HH;
    int d  = threadIdx.x;
    int j  = h_*DH + d;
    const float* xr = x  + (size_t)(b_*SS)*EE;
    const float* wr = Wq + (size_t)j*EE;
    float s = 0.f;
    for (int e = 0; e < EE; e += 4) {
        float4 xv = *(const float4*)(xr + e);
        float4 wv = *(const float4*)(wr + e);
        s += xv.x*wv.x + xv.y*wv.y + xv.z*wv.z + xv.w*wv.w;
    }
    s += bq[j];
    CVEC[bh*DH + d] = s;
    __shared__ float red[64];
    red[d] = s*s; __syncthreads();
    for (int o = 32; o > 0; o >>= 1) { if (d < o) red[d] += red[d+o]; __syncthreads(); }
    if (d == 0) CN2[bh] = fmaxf(red[0], EPSF);
}

// ============================================================
// per-row q stats: QN2 and CQ. grid BH*SQ/8, block 256
// ============================================================
__global__ void qstats_kernel() {
    int row  = blockIdx.x*8 + (threadIdx.x >> 5);
    int lane = threadIdx.x & 31;
    int bh   = row >> 10;
    const float* qr = QS   + (size_t)row*DH;
    const float* cv = CVEC + bh*DH;
    float n2 = 0.f, cq = 0.f;
    #pragma unroll
    for (int d = lane; d < DH; d += 32) {
        float qv = qr[d];
        n2 += qv*qv;
        cq += qv*cv[d];
    }
    #pragma unroll
    for (int o = 16; o > 0; o >>= 1) {
        n2 += __shfl_xor_sync(0xffffffffu, n2, o);
        cq += __shfl_xor_sync(0xffffffffu, cq, o);
    }
    if (lane == 0) { QN2[row] = fmaxf(n2, EPSF); CQg[row] = cq; }
}

// ============================================================
// cls path: ck softmax -> cls_out row (fp16 into VALS). grid BH, block 256
// ============================================================
__global__ void cls_kernel() {
    int bh = blockIdx.x;
    int tid = threadIdx.x;
    const float* Kp = KS + (size_t)bh*SQ*DH;
    const float* Vp = VS + (size_t)bh*SQ*DH;
    __shared__ float p_s[SQ];
    __shared__ float red[256];
    __shared__ float c_s[DH];
    if (tid < DH) c_s[tid] = CVEC[bh*DH + tid];
    __syncthreads();

    float scale = rsqrtf(64.0f * CN2[bh]);
    float lo[4];
    #pragma unroll
    for (int p = 0; p < 4; p++) {
        int j = tid + p*256;
        const float* kr = Kp + (size_t)j*DH;
        float s = 0.f;
        #pragma unroll
        for (int d = 0; d < DH; d += 4) {
            float4 kv = *(const float4*)(kr + d);
            s += c_s[d]*kv.x + c_s[d+1]*kv.y + c_s[d+2]*kv.z + c_s[d+3]*kv.w;
        }
        lo[p] = s * scale;
    }
    float m = fmaxf(fmaxf(lo[0],lo[1]), fmaxf(lo[2],lo[3]));
    red[tid] = m; __syncthreads();
    #pragma unroll
    for (int o = 128; o > 0; o >>= 1) { if (tid < o) red[tid] = fmaxf(red[tid], red[tid+o]); __syncthreads(); }
    m = red[0]; __syncthreads();
    float e[4], s = 0.f;
    #pragma unroll
    for (int p = 0; p < 4; p++) { e[p] = __expf(lo[p] - m); s += e[p]; }
    red[tid] = s; __syncthreads();
    #pragma unroll
    for (int o = 128; o > 0; o >>= 1) { if (tid < o) red[tid] += red[tid+o]; __syncthreads(); }
    float inv = 1.0f / red[0]; __syncthreads();
    #pragma unroll
    for (int p = 0; p < 4; p++) p_s[tid + p*256] = e[p]*inv;
    __syncthreads();

    int d = tid & 63, g = tid >> 6;
    float acc = 0.f;
    for (int j = g*256; j < (g+1)*256; j++) acc += p_s[j] * Vp[(size_t)j*DH + d];
    red[tid] = acc; __syncthreads();
    if (g == 0) {
        float rsum = red[tid] + red[tid+64] + red[tid+128] + red[tid+192];
        int b_ = bh / HH, h_ = bh % HH;
        size_t idx = (size_t)(b_*SS)*EE + h_*DH + d;
        VALSh[idx] = __float2half(rsum);
    }
}

extern "C" void kernel_launch(void* const* d_in, const int* in_sizes, int n_in,
                              void* d_out, int out_size) {
    const float* x  = (const float*)d_in[0];
    const float* Wq = (const float*)d_in[1];
    const float* bq = (const float*)d_in[2];
    const float* Wk = (const float*)d_in[3];
    const float* bk = (const float*)d_in[4];
    const float* Wv = (const float*)d_in[5];
    const float* bv = (const float*)d_in[6];
    const float* Wo = (const float*)d_in[7];
    const float* bo = (const float*)d_in[8];
    const float* Wc = (const float*)d_in[9];
    const float* bc = (const float*)d_in[10];

    float* out  = (float*)d_out;
    float* attn = out + (size_t)BB*SS*EE;

    cudaFuncSetAttribute(proj_mm,    cudaFuncAttributeMaxDynamicSharedMemorySize, 81920);
    cudaFuncSetAttribute(out_mm,     cudaFuncAttributeMaxDynamicSharedMemorySize, 61440);
    cudaFuncSetAttribute(fused_attn, cudaFuncAttributeMaxDynamicSharedMemorySize, 163840);

    bf16 *xh, *xl, *wqh, *wql, *wkh, *wkl, *wvh, *wvl, *wch, *wcl;
    __half *woh, *wol;
    cudaGetSymbolAddress((void**)&xh, XH);   cudaGetSymbolAddress((void**)&xl, XL);
    cudaGetSymbolAddress((void**)&wqh, WqH); cudaGetSymbolAddress((void**)&wql, WqL);
    cudaGetSymbolAddress((void**)&wkh, WkH); cudaGetSymbolAddress((void**)&wkl, WkL);
    cudaGetSymbolAddress((void**)&wvh, WvH); cudaGetSymbolAddress((void**)&wvl, WvL);
    cudaGetSymbolAddress((void**)&wch, WcH); cudaGetSymbolAddress((void**)&wcl, WcL);
    cudaGetSymbolAddress((void**)&woh, WoHh); cudaGetSymbolAddress((void**)&wol, WoLh);

    int nx4 = BB*SS*EE/4, nw4 = EE*EE/4;
    // 1: x conversion
    conv_kernel<<<(nx4+255)/256, 256>>>(x,  xh,  xl,  nx4);
    // 2: Wq + Wk
    convW_kernel<<<dim3((nw4+255)/256, 2), 256>>>(Wq, wqh, wql, Wk, wkh, wkl, nw4);
    // 3: Wv + Wc
    convW_kernel<<<dim3((nw4+255)/256, 2), 256>>>(Wv, wvh, wvl, Wc, wch, wcl, nw4);
    // 4: proj (ncu capture target)
    proj_mm<<<dim3(8,32,4), 256, 81920>>>(bq, bk, bv, bc);
    // 5: Wo conversion (fp16, x64)
    convWo_kernel<<<(nw4+255)/256, 256>>>(Wo, woh, wol, nw4);
    // 6-7: cls projection + q stats
    clsproj_kernel<<<BH, 64>>>(x, Wq, bq);
    qstats_kernel<<<BH*SQ/8, 256>>>();
    // 8: fused attention
    fused_attn<<<dim3(8,BH), 256, 163840>>>(attn);
    // 9: attn normalization in place
    attn_fix<<<BH*SQ, 256>>>(attn);
    // 10: cls output row
    cls_kernel<<<BH, 256>>>();
    // 11: output projection
    out_mm<<<dim3(8,33), 256, 61440>>>(bo, out);
}